// round 14
// baseline (speedup 1.0000x reference)
#include <cuda_runtime.h>
#include <cstdint>

// ---------------- problem constants ----------------
#define MAXN 20000
#define MAXE 512000
#define MAXC 1024
#define NGRAPH 256
#define EPS 1e-5f

// ---------------- scratch (static device memory; no allocs) ----------------
__device__ float g_bufA[(size_t)MAXN * MAXC];   // h
__device__ float g_bufB[(size_t)MAXN * MAXC];   // t raw (pre-BN) / stem xw
__device__ float g_bufC[(size_t)MAXN * MAXC];   // u raw (pre-BN)
__device__ float g_bufD[(size_t)MAXN * MAXC];   // w3 branch raw (+bias)
__device__ float g_aggA[(size_t)MAXN * 512];
__device__ float g_aggB[(size_t)MAXN * 768];
__device__ float g_dinv[MAXN];
__device__ float g_stats [2 * MAXC];            // [sum | sumsq]
__device__ float g_stats2[2 * MAXC];            // [sum2 | sumsq2]
__device__ float g_sc [MAXC];
__device__ float g_sh [MAXC];
__device__ float g_sc2[MAXC];
__device__ float g_sh2[MAXC];
__device__ float g_pool[NGRAPH * MAXC];
__device__ float g_mlp [NGRAPH * MAXC];
__device__ int   g_cnt_i[MAXN];
__device__ int   g_rowstart[MAXN + 1];
__device__ int   g_cursor[MAXN];
__device__ int   g_csr[MAXE];
__device__ int   g_gstart[NGRAPH + 1];

// ---------------- graph preprocessing ----------------
__global__ void cnt_k(const int* __restrict__ dst, int* __restrict__ cnt, int E) {
    int i = blockIdx.x * blockDim.x + threadIdx.x;
    if (i < E) atomicAdd(&cnt[dst[i]], 1);
}
__global__ void prefix_k(const int* __restrict__ cnt, int* __restrict__ rowstart,
                         int* __restrict__ cursor, float* __restrict__ dinv, int n) {
    __shared__ int part[1024];
    const int t = threadIdx.x;
    const int per = (n + 1023) / 1024;
    const int base = t * per;
    int s = 0;
    for (int i = 0; i < per; i++) {
        int idx = base + i;
        if (idx < n) s += cnt[idx];
    }
    part[t] = s;
    __syncthreads();
    for (int off = 1; off < 1024; off <<= 1) {
        int v = (t >= off) ? part[t - off] : 0;
        __syncthreads();
        part[t] += v;
        __syncthreads();
    }
    int excl = (t == 0) ? 0 : part[t - 1];
    int run = excl;
    for (int i = 0; i < per; i++) {
        int idx = base + i;
        if (idx < n) {
            int c = cnt[idx];
            rowstart[idx] = run;
            cursor[idx] = run;
            dinv[idx] = rsqrtf(1.0f + (float)c);
            run += c;
        }
    }
    if (t == 1023) rowstart[n] = excl + s;
}
__global__ void fill_k(const int* __restrict__ src, const int* __restrict__ dst,
                       int* __restrict__ cursor, int* __restrict__ csr, int E) {
    int e = blockIdx.x * blockDim.x + threadIdx.x;
    if (e < E) {
        int pos = atomicAdd(&cursor[dst[e]], 1);
        csr[pos] = src[e];
    }
}
__global__ void gbound_k(const int* __restrict__ batch, int* __restrict__ gstart, int n, int G) {
    int g = blockIdx.x * blockDim.x + threadIdx.x;
    if (g > G) return;
    int lo = 0, hi = n;
    while (lo < hi) {
        int mid = (lo + hi) >> 1;
        if (batch[mid] < g) lo = mid + 1; else hi = mid;
    }
    gstart[g] = lo;
}
__global__ void bnprep_k(const float* __restrict__ stats, const float* __restrict__ gam,
                         const float* __restrict__ bet, float invn,
                         float* __restrict__ sc, float* __restrict__ sh, int C) {
    int c = blockIdx.x * blockDim.x + threadIdx.x;
    if (c >= C) return;
    float m = stats[c] * invn;
    float s = gam[c] * rsqrtf(stats[MAXC + c] * invn - m * m + EPS);
    sc[c] = s;
    sh[c] = bet[c] - m * s;
}

// ---------------- pre/post-GEMM aggregation ----------------
// MODE 0: out[r] = dinv[r]*(dinv[r]*h[r] + sum dinv[s]*h[s])
// MODE 1: same, gathered elements pass through relu(v*sc + sh) first (fused BN apply)
// MODE 2: out[r] = relu( dinv[r]*(dinv[r]*h[r] + sum dinv[s]*h[s]) + bias[c] )  (stem)
// multi-row blocks: blockDim.x = C4 * R rows.
template<int MODE>
__global__ void aggregate_k(const float* __restrict__ h, const int* __restrict__ csr,
                            const int* __restrict__ rowstart, const float* __restrict__ dinv,
                            const float* __restrict__ sc, const float* __restrict__ sh,
                            const float* __restrict__ bias,
                            float* __restrict__ out, int C4, int n) {
    const int rpb = blockDim.x / C4;
    const int rloc = threadIdx.x / C4;
    const int t = threadIdx.x - rloc * C4;
    const int r = blockIdx.x * rpb + rloc;
    if (r >= n) return;
    const float4* base = (const float4*)h;

    float4 sc4, sh4;
    if (MODE == 1) {
        sc4 = *(const float4*)(sc + t * 4);
        sh4 = *(const float4*)(sh + t * 4);
    }
    float4 b4;
    if (MODE == 2) b4 = *(const float4*)(bias + t * 4);

    const float dr = __ldg(&dinv[r]);
    float4 v = base[(size_t)r * C4 + t];
    if (MODE == 1) {
        v.x = fmaxf(v.x * sc4.x + sh4.x, 0.f);
        v.y = fmaxf(v.y * sc4.y + sh4.y, 0.f);
        v.z = fmaxf(v.z * sc4.z + sh4.z, 0.f);
        v.w = fmaxf(v.w * sc4.w + sh4.w, 0.f);
    }
    float4 acc = make_float4(v.x * dr, v.y * dr, v.z * dr, v.w * dr);

    int j   = __ldg(&rowstart[r]);
    int end = __ldg(&rowstart[r + 1]);
    for (; j < end; j++) {
        int s0 = __ldg(&csr[j]);
        float d0 = __ldg(&dinv[s0]);
        float4 v0 = base[(size_t)s0 * C4 + t];
        if (MODE == 1) {
            v0.x = fmaxf(v0.x * sc4.x + sh4.x, 0.f);
            v0.y = fmaxf(v0.y * sc4.y + sh4.y, 0.f);
            v0.z = fmaxf(v0.z * sc4.z + sh4.z, 0.f);
            v0.w = fmaxf(v0.w * sc4.w + sh4.w, 0.f);
        }
        acc.x += v0.x * d0; acc.y += v0.y * d0;
        acc.z += v0.z * d0; acc.w += v0.w * d0;
    }
    float4 o = make_float4(acc.x * dr, acc.y * dr, acc.z * dr, acc.w * dr);
    if (MODE == 2) {
        o.x = fmaxf(o.x + b4.x, 0.f);
        o.y = fmaxf(o.y + b4.y, 0.f);
        o.z = fmaxf(o.z + b4.z, 0.f);
        o.w = fmaxf(o.w + b4.w, 0.f);
    }
    ((float4*)out)[(size_t)r * C4 + t] = o;
}

template<int MODE>
static void launch_agg(cudaStream_t st, const float* h, const int* csr, const int* rowstart,
                       const float* dinv, const float* sc, const float* sh,
                       const float* bias, float* out, int C, int n) {
    int C4 = C / 4;
    int R = 256 / C4; if (R < 1) R = 1;
    int block = C4 * R;
    int grid = (n + R - 1) / R;
    aggregate_k<MODE><<<grid, block, 0, st>>>(h, csr, rowstart, dinv, sc, sh, bias, out, C4, n);
}

// ---------------- residual join (blk0): out = d + relu(c*sc + sh) ----------------
__global__ void join_k(const float* __restrict__ d, const float* __restrict__ c,
                       const float* __restrict__ sc, const float* __restrict__ sh,
                       float* __restrict__ out, int total4, int C4) {
    int idx = blockIdx.x * blockDim.x + threadIdx.x;
    if (idx >= total4) return;
    int t = idx % C4;
    float4 dv = ((const float4*)d)[idx];
    float4 cv = ((const float4*)c)[idx];
    float4 s4 = *(const float4*)(sc + t * 4);
    float4 h4 = *(const float4*)(sh + t * 4);
    float4 o;
    o.x = dv.x + fmaxf(cv.x * s4.x + h4.x, 0.f);
    o.y = dv.y + fmaxf(cv.y * s4.y + h4.y, 0.f);
    o.z = dv.z + fmaxf(cv.z * s4.z + h4.z, 0.f);
    o.w = dv.w + fmaxf(cv.w * s4.w + h4.w, 0.f);
    ((float4*)out)[idx] = o;
}

// ---------------- fused join + segmented mean pool (blk1, C=1024) ----------------
__global__ void pool_fused_k(const float* __restrict__ d, const float* __restrict__ c,
                             const float* __restrict__ sc, const float* __restrict__ sh,
                             const int* __restrict__ gstart, float* __restrict__ pooled) {
    const int g = blockIdx.x;
    const int t = threadIdx.x;
    const float4 s4 = *(const float4*)(sc + t * 4);
    const float4 h4 = *(const float4*)(sh + t * 4);
    int rs = __ldg(&gstart[g]), re = __ldg(&gstart[g + 1]);
    float4 acc = make_float4(0.f, 0.f, 0.f, 0.f);
    for (int r = rs; r < re; r++) {
        float4 dv = ((const float4*)d)[(size_t)r * 256 + t];
        float4 cv = ((const float4*)c)[(size_t)r * 256 + t];
        acc.x += dv.x + fmaxf(cv.x * s4.x + h4.x, 0.f);
        acc.y += dv.y + fmaxf(cv.y * s4.y + h4.y, 0.f);
        acc.z += dv.z + fmaxf(cv.z * s4.z + h4.z, 0.f);
        acc.w += dv.w + fmaxf(cv.w * s4.w + h4.w, 0.f);
    }
    float inv = (re > rs) ? 1.0f / (float)(re - rs) : 0.f;
    float4 o = make_float4(acc.x * inv, acc.y * inv, acc.z * inv, acc.w * inv);
    ((float4*)pooled)[g * 256 + t] = o;
}

// =================== TF32 tensor-core GEMM (256 thr, 4 stages) =====
// MODE 0: C = A@B + bias, relu
// MODE 1: C = A@B raw; atomic col sums into stats [sum | sumsq]
// MODE 3: C = A@B + bias
// MODE 4: C = A@B raw
#define TBM 128
#define TBN 128
#define TBK 16
#define STAGES 4
#define ASTRIDE 20
#define BSTRIDE 136
#define A_TILE (TBM * ASTRIDE)
#define B_TILE (TBK * BSTRIDE)
#define STAGE_FLOATS (A_TILE + B_TILE)
#define GEMM_SMEM (STAGES * STAGE_FLOATS * 4)

__device__ __forceinline__ void cp_async16(uint32_t saddr, const void* gaddr, int srcsize) {
    asm volatile("cp.async.cg.shared.global [%0], [%1], 16, %2;"
                 :: "r"(saddr), "l"(gaddr), "r"(srcsize));
}
__device__ __forceinline__ void mma_tf32(float* c, const uint32_t* a, const uint32_t* b) {
    asm volatile(
        "mma.sync.aligned.m16n8k8.row.col.f32.tf32.tf32.f32 "
        "{%0,%1,%2,%3}, {%4,%5,%6,%7}, {%8,%9}, {%0,%1,%2,%3};\n"
        : "+f"(c[0]), "+f"(c[1]), "+f"(c[2]), "+f"(c[3])
        : "r"(a[0]), "r"(a[1]), "r"(a[2]), "r"(a[3]), "r"(b[0]), "r"(b[1]));
}

__device__ __forceinline__ void load_tile(float* stage, const float* A, const float* B,
                                          int M, int K, int N, int bm0, int bn0, int k0,
                                          int tid) {
    float* sa = stage;
    float* sb = stage + A_TILE;
#pragma unroll
    for (int l = 0; l < 2; l++) {
        int idx = tid + l * 256;
        int arow = idx >> 2, ac4 = (idx & 3) * 4;
        const float* ga = A + (size_t)(bm0 + arow) * K + k0 + ac4;
        uint32_t da = (uint32_t)__cvta_generic_to_shared(sa + arow * ASTRIDE + ac4);
        cp_async16(da, ga, (bm0 + arow) < M ? 16 : 0);
        int bk = idx >> 5, bn4 = (idx & 31) * 4;
        const float* gb = B + (size_t)(k0 + bk) * N + bn0 + bn4;
        uint32_t db = (uint32_t)__cvta_generic_to_shared(sb + bk * BSTRIDE + bn4);
        cp_async16(db, gb, 16);
    }
}

template<int MODE>
__global__ __launch_bounds__(256, 2)
void gemm_tf32_k(const float* __restrict__ A, const float* __restrict__ B,
                 const float* __restrict__ bias,
                 float* __restrict__ stats,
                 float* __restrict__ C, int M, int K, int N) {
    extern __shared__ float sm[];
    const int tid  = threadIdx.x;
    const int lane = tid & 31;
    const int wid  = tid >> 5;
    const int wm   = (wid & 3) * 32;
    const int wn   = (wid >> 2) * 64;
    const int bm0  = blockIdx.y * TBM;
    const int bn0  = blockIdx.x * TBN;

    float acc[2][8][4];
#pragma unroll
    for (int i = 0; i < 2; i++)
#pragma unroll
        for (int j = 0; j < 8; j++)
#pragma unroll
            for (int l = 0; l < 4; l++) acc[i][j][l] = 0.f;

    const int ktiles = K / TBK;

#pragma unroll
    for (int s = 0; s < STAGES - 1; s++) {
        load_tile(sm + s * STAGE_FLOATS, A, B, M, K, N, bm0, bn0, s * TBK, tid);
        asm volatile("cp.async.commit_group;");
    }

    for (int kt = 0; kt < ktiles; kt++) {
        asm volatile("cp.async.wait_group %0;" :: "n"(STAGES - 2));
        __syncthreads();

        int nk = kt + STAGES - 1;
        if (nk < ktiles)
            load_tile(sm + (nk % STAGES) * STAGE_FLOATS, A, B, M, K, N, bm0, bn0, nk * TBK, tid);
        asm volatile("cp.async.commit_group;");

        const float* sa = sm + (kt % STAGES) * STAGE_FLOATS;
        const float* sb = sa + A_TILE;
#pragma unroll
        for (int ks = 0; ks < 2; ks++) {
            const int k0 = ks * 8;
            uint32_t af[2][4], bf[8][2];
#pragma unroll
            for (int tm = 0; tm < 2; tm++) {
                int r0 = wm + tm * 16 + (lane >> 2);
                int c0 = k0 + (lane & 3);
                af[tm][0] = __float_as_uint(sa[r0 * ASTRIDE + c0]);
                af[tm][1] = __float_as_uint(sa[(r0 + 8) * ASTRIDE + c0]);
                af[tm][2] = __float_as_uint(sa[r0 * ASTRIDE + c0 + 4]);
                af[tm][3] = __float_as_uint(sa[(r0 + 8) * ASTRIDE + c0 + 4]);
            }
#pragma unroll
            for (int tn = 0; tn < 8; tn++) {
                int n0 = wn + tn * 8 + (lane >> 2);
                int r0 = k0 + (lane & 3);
                bf[tn][0] = __float_as_uint(sb[r0 * BSTRIDE + n0]);
                bf[tn][1] = __float_as_uint(sb[(r0 + 4) * BSTRIDE + n0]);
            }
#pragma unroll
            for (int tm = 0; tm < 2; tm++)
#pragma unroll
                for (int tn = 0; tn < 8; tn++)
                    mma_tf32(acc[tm][tn], af[tm], bf[tn]);
        }
    }

    // -------- epilogue --------
#pragma unroll
    for (int tm = 0; tm < 2; tm++) {
        int row = bm0 + wm + tm * 16 + (lane >> 2);
#pragma unroll
        for (int tn = 0; tn < 8; tn++) {
            int col = bn0 + wn + tn * 8 + (lane & 3) * 2;
            float v0 = acc[tm][tn][0], v1 = acc[tm][tn][1];
            float v2 = acc[tm][tn][2], v3 = acc[tm][tn][3];
            if (MODE == 0 || MODE == 3) {
                float b0 = __ldg(bias + col), b1 = __ldg(bias + col + 1);
                v0 += b0; v1 += b1; v2 += b0; v3 += b1;
            }
            if (MODE == 0) {
                v0 = fmaxf(v0, 0.f); v1 = fmaxf(v1, 0.f);
                v2 = fmaxf(v2, 0.f); v3 = fmaxf(v3, 0.f);
            }
            if (row < M)     *(float2*)(C + (size_t)row * N + col)       = make_float2(v0, v1);
            if (row + 8 < M) *(float2*)(C + (size_t)(row + 8) * N + col) = make_float2(v2, v3);
        }
    }

    if (MODE == 1) {
#pragma unroll
        for (int tn = 0; tn < 8; tn++) {
            float s0 = acc[0][tn][0] + acc[0][tn][2] + acc[1][tn][0] + acc[1][tn][2];
            float s1 = acc[0][tn][1] + acc[0][tn][3] + acc[1][tn][1] + acc[1][tn][3];
            float q0 = acc[0][tn][0] * acc[0][tn][0] + acc[0][tn][2] * acc[0][tn][2]
                     + acc[1][tn][0] * acc[1][tn][0] + acc[1][tn][2] * acc[1][tn][2];
            float q1 = acc[0][tn][1] * acc[0][tn][1] + acc[0][tn][3] * acc[0][tn][3]
                     + acc[1][tn][1] * acc[1][tn][1] + acc[1][tn][3] * acc[1][tn][3];
#pragma unroll
            for (int st = 16; st >= 4; st >>= 1) {
                s0 += __shfl_down_sync(0xffffffffu, s0, st);
                s1 += __shfl_down_sync(0xffffffffu, s1, st);
                q0 += __shfl_down_sync(0xffffffffu, q0, st);
                q1 += __shfl_down_sync(0xffffffffu, q1, st);
            }
            if (lane < 4) {
                int col = bn0 + wn + tn * 8 + lane * 2;
                atomicAdd(&stats[col], s0);
                atomicAdd(&stats[col + 1], s1);
                atomicAdd(&stats[MAXC + col], q0);
                atomicAdd(&stats[MAXC + col + 1], q1);
            }
        }
    }
}

// ---------------- fp32 tiled SIMT GEMM (final MLP head — exact fp32) ----------------
#define BM 64
#define BN 64
#define BK 16
template<int RELU>
__global__ void gemm_k(const float* __restrict__ A, const float* __restrict__ B,
                       const float* __restrict__ bias, float* __restrict__ C,
                       int M, int K, int N) {
    __shared__ float As2[BK][BM];
    __shared__ float Bs2[BK][BN];
    const int tid = threadIdx.x;
    const int bcol = blockIdx.x, brow = blockIdx.y;
    const int tx = tid & 15, ty = tid >> 4;

    const int arow  = tid >> 2;
    const int acol4 = (tid & 3) * 4;
    const int brow_l = tid >> 4;
    const int bcol4  = (tid & 15) * 4;
    const int grow = brow * BM + arow;

    float acc[4][4];
#pragma unroll
    for (int i = 0; i < 4; i++)
#pragma unroll
        for (int j = 0; j < 4; j++) acc[i][j] = 0.f;

    for (int k0 = 0; k0 < K; k0 += BK) {
        float4 av = make_float4(0.f, 0.f, 0.f, 0.f);
        if (grow < M)
            av = *(const float4*)(A + (size_t)grow * K + k0 + acol4);
        As2[acol4 + 0][arow] = av.x;
        As2[acol4 + 1][arow] = av.y;
        As2[acol4 + 2][arow] = av.z;
        As2[acol4 + 3][arow] = av.w;
        float4 bv = *(const float4*)(B + (size_t)(k0 + brow_l) * N + bcol * BN + bcol4);
        *(float4*)(&Bs2[brow_l][bcol4]) = bv;
        __syncthreads();
#pragma unroll
        for (int k = 0; k < BK; k++) {
            float4 a = *(const float4*)(&As2[k][ty * 4]);
            float4 b = *(const float4*)(&Bs2[k][tx * 4]);
            float ar[4] = {a.x, a.y, a.z, a.w};
            float br[4] = {b.x, b.y, b.z, b.w};
#pragma unroll
            for (int i = 0; i < 4; i++)
#pragma unroll
                for (int j = 0; j < 4; j++)
                    acc[i][j] += ar[i] * br[j];
        }
        __syncthreads();
    }

    const int row0 = brow * BM + ty * 4;
    const int col0 = bcol * BN + tx * 4;
    float4 bb = *(const float4*)(bias + col0);
#pragma unroll
    for (int i = 0; i < 4; i++) {
        int r = row0 + i;
        if (r < M) {
            float4 v;
            v.x = acc[i][0] + bb.x; v.y = acc[i][1] + bb.y;
            v.z = acc[i][2] + bb.z; v.w = acc[i][3] + bb.w;
            if (RELU) {
                v.x = fmaxf(v.x, 0.f); v.y = fmaxf(v.y, 0.f);
                v.z = fmaxf(v.z, 0.f); v.w = fmaxf(v.w, 0.f);
            }
            *(float4*)(C + (size_t)r * N + col0) = v;
        }
    }
}

// ---------------- host-side helpers ----------------
static float* symaddrf(const void* sym) {
    void* p = nullptr;
    cudaGetSymbolAddress(&p, sym);
    return (float*)p;
}
static int* symaddri(const void* sym) {
    void* p = nullptr;
    cudaGetSymbolAddress(&p, sym);
    return (int*)p;
}

template<int MODE>
static void launch_gemm(cudaStream_t st, const float* A, const float* B, const float* bias,
                        float* stats, float* C, int M, int K, int N) {
    static int attr_done = 0;
    if (!attr_done) {
        cudaFuncSetAttribute(gemm_tf32_k<MODE>,
                             cudaFuncAttributeMaxDynamicSharedMemorySize, GEMM_SMEM);
        attr_done = 1;
    }
    dim3 grid(N / TBN, (M + TBM - 1) / TBM);
    gemm_tf32_k<MODE><<<grid, 256, GEMM_SMEM, st>>>(A, B, bias, stats, C, M, K, N);
}

extern "C" void kernel_launch(void* const* d_in, const int* in_sizes, int n_in,
                              void* d_out, int out_size) {
    const float* x     = (const float*)d_in[0];
    const int*   ei    = (const int*)d_in[1];
    const int*   batch = (const int*)d_in[2];
    const float* w0 = (const float*)d_in[3];
    const float* b0 = (const float*)d_in[4];
    const float* mw1 = (const float*)d_in[25];
    const float* mb1 = (const float*)d_in[26];
    const float* mw2 = (const float*)d_in[27];
    const float* mb2 = (const float*)d_in[28];

    const int F = 128;
    const int n = in_sizes[0] / F;          // 20000
    const int E = in_sizes[1] / 2;          // 320000
    const int* src = ei;
    const int* dst = ei + E;
    const float invn = 1.0f / (float)n;

    float* bufA = symaddrf(g_bufA);
    float* bufB = symaddrf(g_bufB);
    float* bufC = symaddrf(g_bufC);
    float* bufD = symaddrf(g_bufD);
    float* aggA = symaddrf(g_aggA);
    float* aggB = symaddrf(g_aggB);
    float* dinv = symaddrf(g_dinv);
    float* stats  = symaddrf(g_stats);
    float* stats2 = symaddrf(g_stats2);
    float* sc  = symaddrf(g_sc);
    float* sh  = symaddrf(g_sh);
    float* sc2 = symaddrf(g_sc2);
    float* sh2 = symaddrf(g_sh2);
    float* pool = symaddrf(g_pool);
    float* mlp  = symaddrf(g_mlp);
    int* cnt_i    = symaddri(g_cnt_i);
    int* rowstart = symaddri(g_rowstart);
    int* cursor   = symaddri(g_cursor);
    int* csr      = symaddri(g_csr);
    int* gstart   = symaddri(g_gstart);

    // side stream + fork/join events (created on first, uncaptured, call)
    static cudaStream_t s2 = nullptr;
    static cudaEvent_t evF[2], evJ[2], evT, evS, evG;
    if (!s2) {
        cudaStreamCreateWithFlags(&s2, cudaStreamNonBlocking);
        for (int i = 0; i < 2; i++) {
            cudaEventCreateWithFlags(&evF[i], cudaEventDisableTiming);
            cudaEventCreateWithFlags(&evJ[i], cudaEventDisableTiming);
        }
        cudaEventCreateWithFlags(&evT, cudaEventDisableTiming);
        cudaEventCreateWithFlags(&evS, cudaEventDisableTiming);
        cudaEventCreateWithFlags(&evG, cudaEventDisableTiming);
    }

    // ---- fork s2 from the capture-origin stream FIRST (capture topology rule) ----
    cudaEventRecord(evT, 0);
    cudaStreamWaitEvent(s2, evT, 0);
    // s2: stem GEMM x@w0 (raw, no CSR dependency) overlapped with CSR build
    launch_gemm<4>(s2, x, w0, nullptr, nullptr, bufB, n, F, 256);
    cudaEventRecord(evS, s2);
    gbound_k<<<2, 256, 0, s2>>>(batch, gstart, n, NGRAPH);
    cudaEventRecord(evG, s2);

    // ---- main: CSR build + dinv (fused into prefix) ----
    cudaMemsetAsync(cnt_i, 0, n * sizeof(int), 0);
    cnt_k<<<(E + 255) / 256, 256>>>(dst, cnt_i, E);
    prefix_k<<<1, 1024>>>(cnt_i, rowstart, cursor, dinv, n);
    fill_k<<<(E + 255) / 256, 256>>>(src, dst, cursor, csr, E);

    // ---- stem: h = relu(agg(x@w0) + b0), 256-wide aggregate with bias+relu ----
    cudaStreamWaitEvent(0, evS, 0);
    launch_agg<2>(0, bufB, csr, rowstart, dinv, nullptr, nullptr, b0, bufA, 256, n);

    // ---- residual blocks ----
    const int Cin_arr[2]  = {256, 512};
    const int Cmid_arr[2] = {384, 768};
    const int Cout_arr[2] = {512, 1024};
    for (int blk = 0; blk < 2; blk++) {
        int base = 5 + blk * 10;
        const float* w1  = (const float*)d_in[base + 0];
        const float* g1  = (const float*)d_in[base + 2];
        const float* be1 = (const float*)d_in[base + 3];
        const float* w2  = (const float*)d_in[base + 4];
        const float* g2  = (const float*)d_in[base + 6];
        const float* be2 = (const float*)d_in[base + 7];
        const float* w3  = (const float*)d_in[base + 8];
        const float* b3  = (const float*)d_in[base + 9];
        int Cin = Cin_arr[blk], Cmid = Cmid_arr[blk], Cout = Cout_arr[blk];

        // aggA = A_hat @ h  (shared by w1 and w3)
        launch_agg<0>(0, bufA, csr, rowstart, dinv, nullptr, nullptr, nullptr, aggA, Cin, n);

        // fork: w3 branch GEMM on side stream (reads aggA only)
        cudaEventRecord(evF[blk], 0);
        cudaStreamWaitEvent(s2, evF[blk], 0);
        launch_gemm<3>(s2, aggA, w3, b3, nullptr, bufD, n, Cin, Cout);
        cudaEventRecord(evJ[blk], s2);

        // main stream: w1 -> stats -> bnprep -> aggB -> w2 -> stats -> bnprep2
        cudaMemsetAsync(stats, 0, 2 * MAXC * sizeof(float), 0);
        launch_gemm<1>(0, aggA, w1, nullptr, stats, bufB, n, Cin, Cmid);
        bnprep_k<<<(Cmid + 255) / 256, 256>>>(stats, g1, be1, invn, sc, sh, Cmid);
        launch_agg<1>(0, bufB, csr, rowstart, dinv, sc, sh, nullptr, aggB, Cmid, n);
        cudaMemsetAsync(stats2, 0, 2 * MAXC * sizeof(float), 0);
        launch_gemm<1>(0, aggB, w2, nullptr, stats2, bufC, n, Cmid, Cout);
        bnprep_k<<<(Cout + 255) / 256, 256>>>(stats2, g2, be2, invn, sc2, sh2, Cout);

        // join
        cudaStreamWaitEvent(0, evJ[blk], 0);
        if (blk == 0) {
            int total4 = n * (Cout / 4);
            join_k<<<(total4 + 255) / 256, 256>>>(bufD, bufC, sc2, sh2, bufA, total4, Cout / 4);
        } else {
            cudaStreamWaitEvent(0, evG, 0);
            pool_fused_k<<<NGRAPH, 256>>>(bufD, bufC, sc2, sh2, gstart, pool);
        }
    }

    // ---- MLP head in exact fp32 (tf32 here pushed rel_err past the 1e-3 gate) ----
    {
        dim3 gmm1(1024 / BN, (NGRAPH + BM - 1) / BM);
        gemm_k<1><<<gmm1, 256>>>(pool, mw1, mb1, mlp, NGRAPH, 1024, 1024);
        dim3 gmm2(768 / BN, (NGRAPH + BM - 1) / BM);
        gemm_k<0><<<gmm2, 256>>>(mlp, mw2, mb2, (float*)d_out, NGRAPH, 1024, 768);
    }
}

// round 15
// speedup vs baseline: 1.0184x; 1.0184x over previous
#include <cuda_runtime.h>
#include <cstdint>

// ---------------- problem constants ----------------
#define MAXN 20000
#define MAXE 512000
#define MAXC 1024
#define NGRAPH 256
#define EPS 1e-5f

// ---------------- scratch (static device memory; no allocs) ----------------
__device__ float g_bufA[(size_t)MAXN * MAXC];   // h
__device__ float g_bufB[(size_t)MAXN * MAXC];   // t raw (pre-BN)
__device__ float g_bufC[(size_t)MAXN * MAXC];   // u raw (pre-BN)
__device__ float g_bufD[(size_t)MAXN * MAXC];   // w3 branch raw (+bias)
__device__ float g_aggA[(size_t)MAXN * 512];
__device__ float g_aggB[(size_t)MAXN * 768];
__device__ float g_dinv[MAXN];
__device__ float g_stats [2 * MAXC];            // [sum | sumsq]
__device__ float g_stats2[2 * MAXC];            // [sum2 | sumsq2]
__device__ float g_sc [MAXC];
__device__ float g_sh [MAXC];
__device__ float g_sc2[MAXC];
__device__ float g_sh2[MAXC];
__device__ float g_pool[NGRAPH * MAXC];
__device__ float g_mlp [NGRAPH * MAXC];
__device__ int   g_cnt_i[MAXN];
__device__ int   g_rowstart[MAXN + 1];
__device__ int   g_cursor[MAXN];
__device__ int   g_csr[MAXE];
__device__ int   g_gstart[NGRAPH + 1];

// ---------------- graph preprocessing ----------------
__global__ void cnt_k(const int* __restrict__ dst, int* __restrict__ cnt, int E) {
    int i = blockIdx.x * blockDim.x + threadIdx.x;
    if (i < E) atomicAdd(&cnt[dst[i]], 1);
}
// chunked coalesced block scan: 1024 threads, chunks of 1024 elements, running carry
__global__ void prefix_k(const int* __restrict__ cnt, int* __restrict__ rowstart,
                         int* __restrict__ cursor, float* __restrict__ dinv, int n) {
    __shared__ int warpsums[32];
    __shared__ int s_carry;
    const int t = threadIdx.x;
    const int lane = t & 31, wid = t >> 5;
    if (t == 0) s_carry = 0;
    __syncthreads();
    for (int base = 0; base < n; base += 1024) {
        int idx = base + t;
        int v = (idx < n) ? cnt[idx] : 0;
        // inclusive warp scan
        int x = v;
#pragma unroll
        for (int off = 1; off < 32; off <<= 1) {
            int y = __shfl_up_sync(0xffffffffu, x, off);
            if (lane >= off) x += y;
        }
        if (lane == 31) warpsums[wid] = x;
        __syncthreads();
        if (wid == 0) {
            int w = warpsums[lane];
#pragma unroll
            for (int off = 1; off < 32; off <<= 1) {
                int y = __shfl_up_sync(0xffffffffu, w, off);
                if (lane >= off) w += y;
            }
            warpsums[lane] = w;
        }
        __syncthreads();
        int excl = s_carry + (wid > 0 ? warpsums[wid - 1] : 0) + x - v;
        if (idx < n) {
            rowstart[idx] = excl;
            cursor[idx] = excl;
            dinv[idx] = rsqrtf(1.0f + (float)v);
        }
        __syncthreads();
        if (t == 1023) s_carry += warpsums[31];
        __syncthreads();
    }
    if (t == 0) rowstart[n] = s_carry;
}
__global__ void fill_k(const int* __restrict__ src, const int* __restrict__ dst,
                       int* __restrict__ cursor, int* __restrict__ csr, int E) {
    int e = blockIdx.x * blockDim.x + threadIdx.x;
    if (e < E) {
        int pos = atomicAdd(&cursor[dst[e]], 1);
        csr[pos] = src[e];
    }
}
__global__ void gbound_k(const int* __restrict__ batch, int* __restrict__ gstart, int n, int G) {
    int g = blockIdx.x * blockDim.x + threadIdx.x;
    if (g > G) return;
    int lo = 0, hi = n;
    while (lo < hi) {
        int mid = (lo + hi) >> 1;
        if (batch[mid] < g) lo = mid + 1; else hi = mid;
    }
    gstart[g] = lo;
}
__global__ void bnprep_k(const float* __restrict__ stats, const float* __restrict__ gam,
                         const float* __restrict__ bet, float invn,
                         float* __restrict__ sc, float* __restrict__ sh, int C) {
    int c = blockIdx.x * blockDim.x + threadIdx.x;
    if (c >= C) return;
    float m = stats[c] * invn;
    float s = gam[c] * rsqrtf(stats[MAXC + c] * invn - m * m + EPS);
    sc[c] = s;
    sh[c] = bet[c] - m * s;
}

// ---------------- pre-GEMM aggregation (multi-row blocks) ----------------
// MODE 0: plain; MODE 1: gathered elements pass relu(v*sc+sh) first (fused BN apply)
template<int MODE>
__global__ void aggregate_k(const float* __restrict__ h, const int* __restrict__ csr,
                            const int* __restrict__ rowstart, const float* __restrict__ dinv,
                            const float* __restrict__ sc, const float* __restrict__ sh,
                            float* __restrict__ out, int C4, int n) {
    const int rpb = blockDim.x / C4;
    const int rloc = threadIdx.x / C4;
    const int t = threadIdx.x - rloc * C4;
    const int r = blockIdx.x * rpb + rloc;
    if (r >= n) return;
    const float4* base = (const float4*)h;

    float4 sc4, sh4;
    if (MODE == 1) {
        sc4 = *(const float4*)(sc + t * 4);
        sh4 = *(const float4*)(sh + t * 4);
    }

    const float dr = __ldg(&dinv[r]);
    float4 v = base[(size_t)r * C4 + t];
    if (MODE == 1) {
        v.x = fmaxf(v.x * sc4.x + sh4.x, 0.f);
        v.y = fmaxf(v.y * sc4.y + sh4.y, 0.f);
        v.z = fmaxf(v.z * sc4.z + sh4.z, 0.f);
        v.w = fmaxf(v.w * sc4.w + sh4.w, 0.f);
    }
    float4 acc = make_float4(v.x * dr, v.y * dr, v.z * dr, v.w * dr);

    int j   = __ldg(&rowstart[r]);
    int end = __ldg(&rowstart[r + 1]);
    for (; j < end; j++) {
        int s0 = __ldg(&csr[j]);
        float d0 = __ldg(&dinv[s0]);
        float4 v0 = base[(size_t)s0 * C4 + t];
        if (MODE == 1) {
            v0.x = fmaxf(v0.x * sc4.x + sh4.x, 0.f);
            v0.y = fmaxf(v0.y * sc4.y + sh4.y, 0.f);
            v0.z = fmaxf(v0.z * sc4.z + sh4.z, 0.f);
            v0.w = fmaxf(v0.w * sc4.w + sh4.w, 0.f);
        }
        acc.x += v0.x * d0; acc.y += v0.y * d0;
        acc.z += v0.z * d0; acc.w += v0.w * d0;
    }
    float4 o = make_float4(acc.x * dr, acc.y * dr, acc.z * dr, acc.w * dr);
    ((float4*)out)[(size_t)r * C4 + t] = o;
}

template<int MODE>
static void launch_agg(cudaStream_t st, const float* h, const int* csr, const int* rowstart,
                       const float* dinv, const float* sc, const float* sh,
                       float* out, int C, int n) {
    int C4 = C / 4;
    int R = 256 / C4; if (R < 1) R = 1;
    int block = C4 * R;
    int grid = (n + R - 1) / R;
    aggregate_k<MODE><<<grid, block, 0, st>>>(h, csr, rowstart, dinv, sc, sh, out, C4, n);
}

// ---------------- residual join (blk0): out = d + relu(c*sc + sh) ----------------
__global__ void join_k(const float* __restrict__ d, const float* __restrict__ c,
                       const float* __restrict__ sc, const float* __restrict__ sh,
                       float* __restrict__ out, int total4, int C4) {
    int idx = blockIdx.x * blockDim.x + threadIdx.x;
    if (idx >= total4) return;
    int t = idx % C4;
    float4 dv = ((const float4*)d)[idx];
    float4 cv = ((const float4*)c)[idx];
    float4 s4 = *(const float4*)(sc + t * 4);
    float4 h4 = *(const float4*)(sh + t * 4);
    float4 o;
    o.x = dv.x + fmaxf(cv.x * s4.x + h4.x, 0.f);
    o.y = dv.y + fmaxf(cv.y * s4.y + h4.y, 0.f);
    o.z = dv.z + fmaxf(cv.z * s4.z + h4.z, 0.f);
    o.w = dv.w + fmaxf(cv.w * s4.w + h4.w, 0.f);
    ((float4*)out)[idx] = o;
}

// ---------------- fused join + segmented mean pool (blk1, C=1024) ----------------
__global__ void pool_fused_k(const float* __restrict__ d, const float* __restrict__ c,
                             const float* __restrict__ sc, const float* __restrict__ sh,
                             const int* __restrict__ gstart, float* __restrict__ pooled) {
    const int g = blockIdx.x;
    const int t = threadIdx.x;
    const float4 s4 = *(const float4*)(sc + t * 4);
    const float4 h4 = *(const float4*)(sh + t * 4);
    int rs = __ldg(&gstart[g]), re = __ldg(&gstart[g + 1]);
    float4 acc = make_float4(0.f, 0.f, 0.f, 0.f);
    for (int r = rs; r < re; r++) {
        float4 dv = ((const float4*)d)[(size_t)r * 256 + t];
        float4 cv = ((const float4*)c)[(size_t)r * 256 + t];
        acc.x += dv.x + fmaxf(cv.x * s4.x + h4.x, 0.f);
        acc.y += dv.y + fmaxf(cv.y * s4.y + h4.y, 0.f);
        acc.z += dv.z + fmaxf(cv.z * s4.z + h4.z, 0.f);
        acc.w += dv.w + fmaxf(cv.w * s4.w + h4.w, 0.f);
    }
    float inv = (re > rs) ? 1.0f / (float)(re - rs) : 0.f;
    float4 o = make_float4(acc.x * inv, acc.y * inv, acc.z * inv, acc.w * inv);
    ((float4*)pooled)[g * 256 + t] = o;
}

// =================== TF32 tensor-core GEMM (256 thr, 4 stages) =====
// MODE 0: C = A@B + bias, relu
// MODE 1: C = A@B raw; atomic col sums into stats [sum | sumsq]
// MODE 3: C = A@B + bias
#define TBM 128
#define TBN 128
#define TBK 16
#define STAGES 4
#define ASTRIDE 20
#define BSTRIDE 136
#define A_TILE (TBM * ASTRIDE)
#define B_TILE (TBK * BSTRIDE)
#define STAGE_FLOATS (A_TILE + B_TILE)
#define GEMM_SMEM (STAGES * STAGE_FLOATS * 4)

__device__ __forceinline__ void cp_async16(uint32_t saddr, const void* gaddr, int srcsize) {
    asm volatile("cp.async.cg.shared.global [%0], [%1], 16, %2;"
                 :: "r"(saddr), "l"(gaddr), "r"(srcsize));
}
__device__ __forceinline__ void mma_tf32(float* c, const uint32_t* a, const uint32_t* b) {
    asm volatile(
        "mma.sync.aligned.m16n8k8.row.col.f32.tf32.tf32.f32 "
        "{%0,%1,%2,%3}, {%4,%5,%6,%7}, {%8,%9}, {%0,%1,%2,%3};\n"
        : "+f"(c[0]), "+f"(c[1]), "+f"(c[2]), "+f"(c[3])
        : "r"(a[0]), "r"(a[1]), "r"(a[2]), "r"(a[3]), "r"(b[0]), "r"(b[1]));
}

__device__ __forceinline__ void load_tile(float* stage, const float* A, const float* B,
                                          int M, int K, int N, int bm0, int bn0, int k0,
                                          int tid) {
    float* sa = stage;
    float* sb = stage + A_TILE;
#pragma unroll
    for (int l = 0; l < 2; l++) {
        int idx = tid + l * 256;
        int arow = idx >> 2, ac4 = (idx & 3) * 4;
        const float* ga = A + (size_t)(bm0 + arow) * K + k0 + ac4;
        uint32_t da = (uint32_t)__cvta_generic_to_shared(sa + arow * ASTRIDE + ac4);
        cp_async16(da, ga, (bm0 + arow) < M ? 16 : 0);
        int bk = idx >> 5, bn4 = (idx & 31) * 4;
        const float* gb = B + (size_t)(k0 + bk) * N + bn0 + bn4;
        uint32_t db = (uint32_t)__cvta_generic_to_shared(sb + bk * BSTRIDE + bn4);
        cp_async16(db, gb, 16);
    }
}

template<int MODE>
__global__ __launch_bounds__(256, 2)
void gemm_tf32_k(const float* __restrict__ A, const float* __restrict__ B,
                 const float* __restrict__ bias,
                 float* __restrict__ stats,
                 float* __restrict__ C, int M, int K, int N) {
    extern __shared__ float sm[];
    const int tid  = threadIdx.x;
    const int lane = tid & 31;
    const int wid  = tid >> 5;
    const int wm   = (wid & 3) * 32;
    const int wn   = (wid >> 2) * 64;
    const int bm0  = blockIdx.y * TBM;
    const int bn0  = blockIdx.x * TBN;

    float acc[2][8][4];
#pragma unroll
    for (int i = 0; i < 2; i++)
#pragma unroll
        for (int j = 0; j < 8; j++)
#pragma unroll
            for (int l = 0; l < 4; l++) acc[i][j][l] = 0.f;

    const int ktiles = K / TBK;

#pragma unroll
    for (int s = 0; s < STAGES - 1; s++) {
        load_tile(sm + s * STAGE_FLOATS, A, B, M, K, N, bm0, bn0, s * TBK, tid);
        asm volatile("cp.async.commit_group;");
    }

    for (int kt = 0; kt < ktiles; kt++) {
        asm volatile("cp.async.wait_group %0;" :: "n"(STAGES - 2));
        __syncthreads();

        int nk = kt + STAGES - 1;
        if (nk < ktiles)
            load_tile(sm + (nk % STAGES) * STAGE_FLOATS, A, B, M, K, N, bm0, bn0, nk * TBK, tid);
        asm volatile("cp.async.commit_group;");

        const float* sa = sm + (kt % STAGES) * STAGE_FLOATS;
        const float* sb = sa + A_TILE;
#pragma unroll
        for (int ks = 0; ks < 2; ks++) {
            const int k0 = ks * 8;
            uint32_t af[2][4], bf[8][2];
#pragma unroll
            for (int tm = 0; tm < 2; tm++) {
                int r0 = wm + tm * 16 + (lane >> 2);
                int c0 = k0 + (lane & 3);
                af[tm][0] = __float_as_uint(sa[r0 * ASTRIDE + c0]);
                af[tm][1] = __float_as_uint(sa[(r0 + 8) * ASTRIDE + c0]);
                af[tm][2] = __float_as_uint(sa[r0 * ASTRIDE + c0 + 4]);
                af[tm][3] = __float_as_uint(sa[(r0 + 8) * ASTRIDE + c0 + 4]);
            }
#pragma unroll
            for (int tn = 0; tn < 8; tn++) {
                int n0 = wn + tn * 8 + (lane >> 2);
                int r0 = k0 + (lane & 3);
                bf[tn][0] = __float_as_uint(sb[r0 * BSTRIDE + n0]);
                bf[tn][1] = __float_as_uint(sb[(r0 + 4) * BSTRIDE + n0]);
            }
#pragma unroll
            for (int tm = 0; tm < 2; tm++)
#pragma unroll
                for (int tn = 0; tn < 8; tn++)
                    mma_tf32(acc[tm][tn], af[tm], bf[tn]);
        }
    }

    // -------- epilogue --------
#pragma unroll
    for (int tm = 0; tm < 2; tm++) {
        int row = bm0 + wm + tm * 16 + (lane >> 2);
#pragma unroll
        for (int tn = 0; tn < 8; tn++) {
            int col = bn0 + wn + tn * 8 + (lane & 3) * 2;
            float v0 = acc[tm][tn][0], v1 = acc[tm][tn][1];
            float v2 = acc[tm][tn][2], v3 = acc[tm][tn][3];
            if (MODE == 0 || MODE == 3) {
                float b0 = __ldg(bias + col), b1 = __ldg(bias + col + 1);
                v0 += b0; v1 += b1; v2 += b0; v3 += b1;
            }
            if (MODE == 0) {
                v0 = fmaxf(v0, 0.f); v1 = fmaxf(v1, 0.f);
                v2 = fmaxf(v2, 0.f); v3 = fmaxf(v3, 0.f);
            }
            if (row < M)     *(float2*)(C + (size_t)row * N + col)       = make_float2(v0, v1);
            if (row + 8 < M) *(float2*)(C + (size_t)(row + 8) * N + col) = make_float2(v2, v3);
        }
    }

    if (MODE == 1) {
#pragma unroll
        for (int tn = 0; tn < 8; tn++) {
            float s0 = acc[0][tn][0] + acc[0][tn][2] + acc[1][tn][0] + acc[1][tn][2];
            float s1 = acc[0][tn][1] + acc[0][tn][3] + acc[1][tn][1] + acc[1][tn][3];
            float q0 = acc[0][tn][0] * acc[0][tn][0] + acc[0][tn][2] * acc[0][tn][2]
                     + acc[1][tn][0] * acc[1][tn][0] + acc[1][tn][2] * acc[1][tn][2];
            float q1 = acc[0][tn][1] * acc[0][tn][1] + acc[0][tn][3] * acc[0][tn][3]
                     + acc[1][tn][1] * acc[1][tn][1] + acc[1][tn][3] * acc[1][tn][3];
#pragma unroll
            for (int st = 16; st >= 4; st >>= 1) {
                s0 += __shfl_down_sync(0xffffffffu, s0, st);
                s1 += __shfl_down_sync(0xffffffffu, s1, st);
                q0 += __shfl_down_sync(0xffffffffu, q0, st);
                q1 += __shfl_down_sync(0xffffffffu, q1, st);
            }
            if (lane < 4) {
                int col = bn0 + wn + tn * 8 + lane * 2;
                atomicAdd(&stats[col], s0);
                atomicAdd(&stats[col + 1], s1);
                atomicAdd(&stats[MAXC + col], q0);
                atomicAdd(&stats[MAXC + col + 1], q1);
            }
        }
    }
}

// ---------------- fp32 tiled SIMT GEMM (final MLP head — exact fp32) ----------------
#define BM 64
#define BN 64
#define BK 16
template<int RELU>
__global__ void gemm_k(const float* __restrict__ A, const float* __restrict__ B,
                       const float* __restrict__ bias, float* __restrict__ C,
                       int M, int K, int N) {
    __shared__ float As2[BK][BM];
    __shared__ float Bs2[BK][BN];
    const int tid = threadIdx.x;
    const int bcol = blockIdx.x, brow = blockIdx.y;
    const int tx = tid & 15, ty = tid >> 4;

    const int arow  = tid >> 2;
    const int acol4 = (tid & 3) * 4;
    const int brow_l = tid >> 4;
    const int bcol4  = (tid & 15) * 4;
    const int grow = brow * BM + arow;

    float acc[4][4];
#pragma unroll
    for (int i = 0; i < 4; i++)
#pragma unroll
        for (int j = 0; j < 4; j++) acc[i][j] = 0.f;

    for (int k0 = 0; k0 < K; k0 += BK) {
        float4 av = make_float4(0.f, 0.f, 0.f, 0.f);
        if (grow < M)
            av = *(const float4*)(A + (size_t)grow * K + k0 + acol4);
        As2[acol4 + 0][arow] = av.x;
        As2[acol4 + 1][arow] = av.y;
        As2[acol4 + 2][arow] = av.z;
        As2[acol4 + 3][arow] = av.w;
        float4 bv = *(const float4*)(B + (size_t)(k0 + brow_l) * N + bcol * BN + bcol4);
        *(float4*)(&Bs2[brow_l][bcol4]) = bv;
        __syncthreads();
#pragma unroll
        for (int k = 0; k < BK; k++) {
            float4 a = *(const float4*)(&As2[k][ty * 4]);
            float4 b = *(const float4*)(&Bs2[k][tx * 4]);
            float ar[4] = {a.x, a.y, a.z, a.w};
            float br[4] = {b.x, b.y, b.z, b.w};
#pragma unroll
            for (int i = 0; i < 4; i++)
#pragma unroll
                for (int j = 0; j < 4; j++)
                    acc[i][j] += ar[i] * br[j];
        }
        __syncthreads();
    }

    const int row0 = brow * BM + ty * 4;
    const int col0 = bcol * BN + tx * 4;
    float4 bb = *(const float4*)(bias + col0);
#pragma unroll
    for (int i = 0; i < 4; i++) {
        int r = row0 + i;
        if (r < M) {
            float4 v;
            v.x = acc[i][0] + bb.x; v.y = acc[i][1] + bb.y;
            v.z = acc[i][2] + bb.z; v.w = acc[i][3] + bb.w;
            if (RELU) {
                v.x = fmaxf(v.x, 0.f); v.y = fmaxf(v.y, 0.f);
                v.z = fmaxf(v.z, 0.f); v.w = fmaxf(v.w, 0.f);
            }
            *(float4*)(C + (size_t)r * N + col0) = v;
        }
    }
}

// ---------------- host-side helpers ----------------
static float* symaddrf(const void* sym) {
    void* p = nullptr;
    cudaGetSymbolAddress(&p, sym);
    return (float*)p;
}
static int* symaddri(const void* sym) {
    void* p = nullptr;
    cudaGetSymbolAddress(&p, sym);
    return (int*)p;
}

template<int MODE>
static void launch_gemm(cudaStream_t st, const float* A, const float* B, const float* bias,
                        float* stats, float* C, int M, int K, int N) {
    static int attr_done = 0;
    if (!attr_done) {
        cudaFuncSetAttribute(gemm_tf32_k<MODE>,
                             cudaFuncAttributeMaxDynamicSharedMemorySize, GEMM_SMEM);
        attr_done = 1;
    }
    dim3 grid(N / TBN, (M + TBM - 1) / TBM);
    gemm_tf32_k<MODE><<<grid, 256, GEMM_SMEM, st>>>(A, B, bias, stats, C, M, K, N);
}

extern "C" void kernel_launch(void* const* d_in, const int* in_sizes, int n_in,
                              void* d_out, int out_size) {
    const float* x     = (const float*)d_in[0];
    const int*   ei    = (const int*)d_in[1];
    const int*   batch = (const int*)d_in[2];
    const float* w0 = (const float*)d_in[3];
    const float* b0 = (const float*)d_in[4];
    const float* mw1 = (const float*)d_in[25];
    const float* mb1 = (const float*)d_in[26];
    const float* mw2 = (const float*)d_in[27];
    const float* mb2 = (const float*)d_in[28];

    const int F = 128;
    const int n = in_sizes[0] / F;          // 20000
    const int E = in_sizes[1] / 2;          // 320000
    const int* src = ei;
    const int* dst = ei + E;
    const float invn = 1.0f / (float)n;

    float* bufA = symaddrf(g_bufA);
    float* bufB = symaddrf(g_bufB);
    float* bufC = symaddrf(g_bufC);
    float* bufD = symaddrf(g_bufD);
    float* aggA = symaddrf(g_aggA);
    float* aggB = symaddrf(g_aggB);
    float* dinv = symaddrf(g_dinv);
    float* stats  = symaddrf(g_stats);
    float* stats2 = symaddrf(g_stats2);
    float* sc  = symaddrf(g_sc);
    float* sh  = symaddrf(g_sh);
    float* sc2 = symaddrf(g_sc2);
    float* sh2 = symaddrf(g_sh2);
    float* pool = symaddrf(g_pool);
    float* mlp  = symaddrf(g_mlp);
    int* cnt_i    = symaddri(g_cnt_i);
    int* rowstart = symaddri(g_rowstart);
    int* cursor   = symaddri(g_cursor);
    int* csr      = symaddri(g_csr);
    int* gstart   = symaddri(g_gstart);

    // side stream + fork/join events (created on first, uncaptured, call)
    static cudaStream_t s2 = nullptr;
    static cudaEvent_t evF[2], evJ[2], evT, evG;
    if (!s2) {
        cudaStreamCreateWithFlags(&s2, cudaStreamNonBlocking);
        for (int i = 0; i < 2; i++) {
            cudaEventCreateWithFlags(&evF[i], cudaEventDisableTiming);
            cudaEventCreateWithFlags(&evJ[i], cudaEventDisableTiming);
        }
        cudaEventCreateWithFlags(&evT, cudaEventDisableTiming);
        cudaEventCreateWithFlags(&evG, cudaEventDisableTiming);
    }

    // ---- fork s2 from capture-origin stream FIRST (capture topology rule) ----
    cudaEventRecord(evT, 0);
    cudaStreamWaitEvent(s2, evT, 0);
    gbound_k<<<2, 256, 0, s2>>>(batch, gstart, n, NGRAPH);
    cudaEventRecord(evG, s2);

    // ---- CSR build + dinv (coalesced chunked scan) ----
    cudaMemsetAsync(cnt_i, 0, n * sizeof(int), 0);
    cnt_k<<<(E + 255) / 256, 256>>>(dst, cnt_i, E);
    prefix_k<<<1, 1024>>>(cnt_i, rowstart, cursor, dinv, n);
    fill_k<<<(E + 255) / 256, 256>>>(src, dst, cursor, csr, E);

    // ---- stem: h = relu(agg(x) @ w0 + b0) ----
    launch_agg<0>(0, x, csr, rowstart, dinv, nullptr, nullptr, aggA, F, n);
    launch_gemm<0>(0, aggA, w0, b0, nullptr, bufA, n, F, 256);

    // ---- residual blocks ----
    const int Cin_arr[2]  = {256, 512};
    const int Cmid_arr[2] = {384, 768};
    const int Cout_arr[2] = {512, 1024};
    for (int blk = 0; blk < 2; blk++) {
        int base = 5 + blk * 10;
        const float* w1  = (const float*)d_in[base + 0];
        const float* g1  = (const float*)d_in[base + 2];
        const float* be1 = (const float*)d_in[base + 3];
        const float* w2  = (const float*)d_in[base + 4];
        const float* g2  = (const float*)d_in[base + 6];
        const float* be2 = (const float*)d_in[base + 7];
        const float* w3  = (const float*)d_in[base + 8];
        const float* b3  = (const float*)d_in[base + 9];
        int Cin = Cin_arr[blk], Cmid = Cmid_arr[blk], Cout = Cout_arr[blk];

        // aggA = A_hat @ h  (shared by w1 and w3)
        launch_agg<0>(0, bufA, csr, rowstart, dinv, nullptr, nullptr, aggA, Cin, n);

        // fork: w3 branch GEMM on side stream (reads aggA only)
        cudaEventRecord(evF[blk], 0);
        cudaStreamWaitEvent(s2, evF[blk], 0);
        launch_gemm<3>(s2, aggA, w3, b3, nullptr, bufD, n, Cin, Cout);
        cudaEventRecord(evJ[blk], s2);

        // main stream: w1 -> stats -> bnprep -> aggB -> w2 -> stats -> bnprep2
        cudaMemsetAsync(stats, 0, 2 * MAXC * sizeof(float), 0);
        launch_gemm<1>(0, aggA, w1, nullptr, stats, bufB, n, Cin, Cmid);
        bnprep_k<<<(Cmid + 255) / 256, 256>>>(stats, g1, be1, invn, sc, sh, Cmid);
        launch_agg<1>(0, bufB, csr, rowstart, dinv, sc, sh, aggB, Cmid, n);
        cudaMemsetAsync(stats2, 0, 2 * MAXC * sizeof(float), 0);
        launch_gemm<1>(0, aggB, w2, nullptr, stats2, bufC, n, Cmid, Cout);
        bnprep_k<<<(Cout + 255) / 256, 256>>>(stats2, g2, be2, invn, sc2, sh2, Cout);

        // join
        cudaStreamWaitEvent(0, evJ[blk], 0);
        if (blk == 0) {
            int total4 = n * (Cout / 4);
            join_k<<<(total4 + 255) / 256, 256>>>(bufD, bufC, sc2, sh2, bufA, total4, Cout / 4);
        } else {
            cudaStreamWaitEvent(0, evG, 0);
            pool_fused_k<<<NGRAPH, 256>>>(bufD, bufC, sc2, sh2, gstart, pool);
        }
    }

    // ---- MLP head in exact fp32 (tf32 here pushed rel_err past the 1e-3 gate) ----
    {
        dim3 gmm1(1024 / BN, (NGRAPH + BM - 1) / BM);
        gemm_k<1><<<gmm1, 256>>>(pool, mw1, mb1, mlp, NGRAPH, 1024, 1024);
        dim3 gmm2(768 / BN, (NGRAPH + BM - 1) / BM);
        gemm_k<0><<<gmm2, 256>>>(mlp, mw2, mb2, (float*)d_out, NGRAPH, 1024, 768);
    }
}

// round 16
// speedup vs baseline: 1.0280x; 1.0094x over previous
#include <cuda_runtime.h>
#include <cstdint>

// ---------------- problem constants ----------------
#define MAXN 20000
#define MAXE 512000
#define MAXC 1024
#define NGRAPH 256
#define EPS 1e-5f

// ---------------- scratch (static device memory; no allocs) ----------------
__device__ float g_bufA[(size_t)MAXN * MAXC];   // h
__device__ float g_bufB[(size_t)MAXN * MAXC];   // t raw (pre-BN)
__device__ float g_bufC[(size_t)MAXN * MAXC];   // u raw (pre-BN)
__device__ float g_bufD[(size_t)MAXN * MAXC];   // w3 branch raw (+bias)
__device__ float g_aggA[(size_t)MAXN * 512];
__device__ float g_aggB[(size_t)MAXN * 768];
__device__ float g_dinv[MAXN];
__device__ float g_stats [2 * MAXC];            // [sum | sumsq]
__device__ float g_stats2[2 * MAXC];            // [sum2 | sumsq2]
__device__ float g_sc [MAXC];
__device__ float g_sh [MAXC];
__device__ float g_sc2[MAXC];
__device__ float g_sh2[MAXC];
__device__ float g_pool[NGRAPH * MAXC];
__device__ float g_mlp [NGRAPH * MAXC];
__device__ int   g_cnt_i[MAXN];
__device__ int   g_rowstart[MAXN + 1];
__device__ int   g_cursor[MAXN];
__device__ int   g_csr[MAXE];
__device__ int   g_gstart[NGRAPH + 1];

// ---------------- graph preprocessing ----------------
__global__ void cnt_k(const int* __restrict__ dst, int* __restrict__ cnt, int E) {
    int i = blockIdx.x * blockDim.x + threadIdx.x;
    if (i < E) atomicAdd(&cnt[dst[i]], 1);
}
// chunked coalesced block scan: 1024 threads, chunks of 1024 elements, running carry
__global__ void prefix_k(const int* __restrict__ cnt, int* __restrict__ rowstart,
                         int* __restrict__ cursor, float* __restrict__ dinv, int n) {
    __shared__ int warpsums[32];
    __shared__ int s_carry;
    const int t = threadIdx.x;
    const int lane = t & 31, wid = t >> 5;
    if (t == 0) s_carry = 0;
    __syncthreads();
    for (int base = 0; base < n; base += 1024) {
        int idx = base + t;
        int v = (idx < n) ? cnt[idx] : 0;
        int x = v;
#pragma unroll
        for (int off = 1; off < 32; off <<= 1) {
            int y = __shfl_up_sync(0xffffffffu, x, off);
            if (lane >= off) x += y;
        }
        if (lane == 31) warpsums[wid] = x;
        __syncthreads();
        if (wid == 0) {
            int w = warpsums[lane];
#pragma unroll
            for (int off = 1; off < 32; off <<= 1) {
                int y = __shfl_up_sync(0xffffffffu, w, off);
                if (lane >= off) w += y;
            }
            warpsums[lane] = w;
        }
        __syncthreads();
        int excl = s_carry + (wid > 0 ? warpsums[wid - 1] : 0) + x - v;
        if (idx < n) {
            rowstart[idx] = excl;
            cursor[idx] = excl;
            dinv[idx] = rsqrtf(1.0f + (float)v);
        }
        __syncthreads();
        if (t == 1023) s_carry += warpsums[31];
        __syncthreads();
    }
    if (t == 0) rowstart[n] = s_carry;
}
__global__ void fill_k(const int* __restrict__ src, const int* __restrict__ dst,
                       int* __restrict__ cursor, int* __restrict__ csr, int E) {
    int e = blockIdx.x * blockDim.x + threadIdx.x;
    if (e < E) {
        int pos = atomicAdd(&cursor[dst[e]], 1);
        csr[pos] = src[e];
    }
}
__global__ void gbound_k(const int* __restrict__ batch, int* __restrict__ gstart, int n, int G) {
    int g = blockIdx.x * blockDim.x + threadIdx.x;
    if (g > G) return;
    int lo = 0, hi = n;
    while (lo < hi) {
        int mid = (lo + hi) >> 1;
        if (batch[mid] < g) lo = mid + 1; else hi = mid;
    }
    gstart[g] = lo;
}
__global__ void bnprep_k(const float* __restrict__ stats, const float* __restrict__ gam,
                         const float* __restrict__ bet, float invn,
                         float* __restrict__ sc, float* __restrict__ sh, int C) {
    int c = blockIdx.x * blockDim.x + threadIdx.x;
    if (c >= C) return;
    float m = stats[c] * invn;
    float s = gam[c] * rsqrtf(stats[MAXC + c] * invn - m * m + EPS);
    sc[c] = s;
    sh[c] = bet[c] - m * s;
}

// ---------------- pre-GEMM aggregation (multi-row blocks) ----------------
// MODE 0: plain; MODE 1: gathered elements pass relu(v*sc+sh) first (fused BN apply)
template<int MODE>
__global__ void aggregate_k(const float* __restrict__ h, const int* __restrict__ csr,
                            const int* __restrict__ rowstart, const float* __restrict__ dinv,
                            const float* __restrict__ sc, const float* __restrict__ sh,
                            float* __restrict__ out, int C4, int n) {
    const int rpb = blockDim.x / C4;
    const int rloc = threadIdx.x / C4;
    const int t = threadIdx.x - rloc * C4;
    const int r = blockIdx.x * rpb + rloc;
    if (r >= n) return;
    const float4* base = (const float4*)h;

    float4 sc4, sh4;
    if (MODE == 1) {
        sc4 = *(const float4*)(sc + t * 4);
        sh4 = *(const float4*)(sh + t * 4);
    }

    const float dr = __ldg(&dinv[r]);
    float4 v = base[(size_t)r * C4 + t];
    if (MODE == 1) {
        v.x = fmaxf(v.x * sc4.x + sh4.x, 0.f);
        v.y = fmaxf(v.y * sc4.y + sh4.y, 0.f);
        v.z = fmaxf(v.z * sc4.z + sh4.z, 0.f);
        v.w = fmaxf(v.w * sc4.w + sh4.w, 0.f);
    }
    float4 acc = make_float4(v.x * dr, v.y * dr, v.z * dr, v.w * dr);

    int j   = __ldg(&rowstart[r]);
    int end = __ldg(&rowstart[r + 1]);
    for (; j < end; j++) {
        int s0 = __ldg(&csr[j]);
        float d0 = __ldg(&dinv[s0]);
        float4 v0 = base[(size_t)s0 * C4 + t];
        if (MODE == 1) {
            v0.x = fmaxf(v0.x * sc4.x + sh4.x, 0.f);
            v0.y = fmaxf(v0.y * sc4.y + sh4.y, 0.f);
            v0.z = fmaxf(v0.z * sc4.z + sh4.z, 0.f);
            v0.w = fmaxf(v0.w * sc4.w + sh4.w, 0.f);
        }
        acc.x += v0.x * d0; acc.y += v0.y * d0;
        acc.z += v0.z * d0; acc.w += v0.w * d0;
    }
    float4 o = make_float4(acc.x * dr, acc.y * dr, acc.z * dr, acc.w * dr);
    ((float4*)out)[(size_t)r * C4 + t] = o;
}

template<int MODE>
static void launch_agg(cudaStream_t st, const float* h, const int* csr, const int* rowstart,
                       const float* dinv, const float* sc, const float* sh,
                       float* out, int C, int n) {
    int C4 = C / 4;
    int R = 256 / C4; if (R < 1) R = 1;
    int block = C4 * R;
    int grid = (n + R - 1) / R;
    aggregate_k<MODE><<<grid, block, 0, st>>>(h, csr, rowstart, dinv, sc, sh, out, C4, n);
}

// ---------------- residual join (blk0): out = d + relu(c*sc + sh) ----------------
__global__ void join_k(const float* __restrict__ d, const float* __restrict__ c,
                       const float* __restrict__ sc, const float* __restrict__ sh,
                       float* __restrict__ out, int total4, int C4) {
    int idx = blockIdx.x * blockDim.x + threadIdx.x;
    if (idx >= total4) return;
    int t = idx % C4;
    float4 dv = ((const float4*)d)[idx];
    float4 cv = ((const float4*)c)[idx];
    float4 s4 = *(const float4*)(sc + t * 4);
    float4 h4 = *(const float4*)(sh + t * 4);
    float4 o;
    o.x = dv.x + fmaxf(cv.x * s4.x + h4.x, 0.f);
    o.y = dv.y + fmaxf(cv.y * s4.y + h4.y, 0.f);
    o.z = dv.z + fmaxf(cv.z * s4.z + h4.z, 0.f);
    o.w = dv.w + fmaxf(cv.w * s4.w + h4.w, 0.f);
    ((float4*)out)[idx] = o;
}

// ---------------- fused join + segmented mean pool (blk1, C=1024) ----------------
// grid (4, NGRAPH): each CTA covers 64 float4 columns (256 floats) of one graph;
// 256 threads = 4 row-groups x 64 col-threads, smem reduction across row-groups.
__global__ void pool_fused_k(const float* __restrict__ d, const float* __restrict__ c,
                             const float* __restrict__ sc, const float* __restrict__ sh,
                             const int* __restrict__ gstart, float* __restrict__ pooled) {
    __shared__ float4 red[256];
    const int g  = blockIdx.y;
    const int cb = blockIdx.x * 64;          // float4 col base within the 256
    const int rg = threadIdx.x >> 6;         // 0..3 row-group
    const int cl = threadIdx.x & 63;         // 0..63 col within slice
    const int t  = cb + cl;                  // global float4 col (0..255)
    const float4 s4 = *(const float4*)(sc + t * 4);
    const float4 h4 = *(const float4*)(sh + t * 4);
    int rs = __ldg(&gstart[g]), re = __ldg(&gstart[g + 1]);
    float4 acc = make_float4(0.f, 0.f, 0.f, 0.f);
    for (int r = rs + rg; r < re; r += 4) {
        float4 dv = ((const float4*)d)[(size_t)r * 256 + t];
        float4 cv = ((const float4*)c)[(size_t)r * 256 + t];
        acc.x += dv.x + fmaxf(cv.x * s4.x + h4.x, 0.f);
        acc.y += dv.y + fmaxf(cv.y * s4.y + h4.y, 0.f);
        acc.z += dv.z + fmaxf(cv.z * s4.z + h4.z, 0.f);
        acc.w += dv.w + fmaxf(cv.w * s4.w + h4.w, 0.f);
    }
    red[threadIdx.x] = acc;
    __syncthreads();
    if (rg == 0) {
#pragma unroll
        for (int q = 1; q < 4; q++) {
            float4 v = red[q * 64 + cl];
            acc.x += v.x; acc.y += v.y; acc.z += v.z; acc.w += v.w;
        }
        float inv = (re > rs) ? 1.0f / (float)(re - rs) : 0.f;
        float4 o = make_float4(acc.x * inv, acc.y * inv, acc.z * inv, acc.w * inv);
        ((float4*)pooled)[g * 256 + t] = o;
    }
}

// =================== TF32 tensor-core GEMM (256 thr, 4 stages) =====
// MODE 0: C = A@B + bias, relu
// MODE 1: C = A@B raw; atomic col sums into stats [sum | sumsq]
// MODE 3: C = A@B + bias
#define TBM 128
#define TBN 128
#define TBK 16
#define STAGES 4
#define ASTRIDE 20
#define BSTRIDE 136
#define A_TILE (TBM * ASTRIDE)
#define B_TILE (TBK * BSTRIDE)
#define STAGE_FLOATS (A_TILE + B_TILE)
#define GEMM_SMEM (STAGES * STAGE_FLOATS * 4)

__device__ __forceinline__ void cp_async16(uint32_t saddr, const void* gaddr, int srcsize) {
    asm volatile("cp.async.cg.shared.global [%0], [%1], 16, %2;"
                 :: "r"(saddr), "l"(gaddr), "r"(srcsize));
}
__device__ __forceinline__ void mma_tf32(float* c, const uint32_t* a, const uint32_t* b) {
    asm volatile(
        "mma.sync.aligned.m16n8k8.row.col.f32.tf32.tf32.f32 "
        "{%0,%1,%2,%3}, {%4,%5,%6,%7}, {%8,%9}, {%0,%1,%2,%3};\n"
        : "+f"(c[0]), "+f"(c[1]), "+f"(c[2]), "+f"(c[3])
        : "r"(a[0]), "r"(a[1]), "r"(a[2]), "r"(a[3]), "r"(b[0]), "r"(b[1]));
}

__device__ __forceinline__ void load_tile(float* stage, const float* A, const float* B,
                                          int M, int K, int N, int bm0, int bn0, int k0,
                                          int tid) {
    float* sa = stage;
    float* sb = stage + A_TILE;
#pragma unroll
    for (int l = 0; l < 2; l++) {
        int idx = tid + l * 256;
        int arow = idx >> 2, ac4 = (idx & 3) * 4;
        const float* ga = A + (size_t)(bm0 + arow) * K + k0 + ac4;
        uint32_t da = (uint32_t)__cvta_generic_to_shared(sa + arow * ASTRIDE + ac4);
        cp_async16(da, ga, (bm0 + arow) < M ? 16 : 0);
        int bk = idx >> 5, bn4 = (idx & 31) * 4;
        const float* gb = B + (size_t)(k0 + bk) * N + bn0 + bn4;
        uint32_t db = (uint32_t)__cvta_generic_to_shared(sb + bk * BSTRIDE + bn4);
        cp_async16(db, gb, 16);
    }
}

template<int MODE>
__global__ __launch_bounds__(256, 2)
void gemm_tf32_k(const float* __restrict__ A, const float* __restrict__ B,
                 const float* __restrict__ bias,
                 float* __restrict__ stats,
                 float* __restrict__ C, int M, int K, int N) {
    extern __shared__ float sm[];
    const int tid  = threadIdx.x;
    const int lane = tid & 31;
    const int wid  = tid >> 5;
    const int wm   = (wid & 3) * 32;
    const int wn   = (wid >> 2) * 64;
    const int bm0  = blockIdx.y * TBM;
    const int bn0  = blockIdx.x * TBN;

    float acc[2][8][4];
#pragma unroll
    for (int i = 0; i < 2; i++)
#pragma unroll
        for (int j = 0; j < 8; j++)
#pragma unroll
            for (int l = 0; l < 4; l++) acc[i][j][l] = 0.f;

    const int ktiles = K / TBK;

#pragma unroll
    for (int s = 0; s < STAGES - 1; s++) {
        load_tile(sm + s * STAGE_FLOATS, A, B, M, K, N, bm0, bn0, s * TBK, tid);
        asm volatile("cp.async.commit_group;");
    }

    for (int kt = 0; kt < ktiles; kt++) {
        asm volatile("cp.async.wait_group %0;" :: "n"(STAGES - 2));
        __syncthreads();

        int nk = kt + STAGES - 1;
        if (nk < ktiles)
            load_tile(sm + (nk % STAGES) * STAGE_FLOATS, A, B, M, K, N, bm0, bn0, nk * TBK, tid);
        asm volatile("cp.async.commit_group;");

        const float* sa = sm + (kt % STAGES) * STAGE_FLOATS;
        const float* sb = sa + A_TILE;
#pragma unroll
        for (int ks = 0; ks < 2; ks++) {
            const int k0 = ks * 8;
            uint32_t af[2][4], bf[8][2];
#pragma unroll
            for (int tm = 0; tm < 2; tm++) {
                int r0 = wm + tm * 16 + (lane >> 2);
                int c0 = k0 + (lane & 3);
                af[tm][0] = __float_as_uint(sa[r0 * ASTRIDE + c0]);
                af[tm][1] = __float_as_uint(sa[(r0 + 8) * ASTRIDE + c0]);
                af[tm][2] = __float_as_uint(sa[r0 * ASTRIDE + c0 + 4]);
                af[tm][3] = __float_as_uint(sa[(r0 + 8) * ASTRIDE + c0 + 4]);
            }
#pragma unroll
            for (int tn = 0; tn < 8; tn++) {
                int n0 = wn + tn * 8 + (lane >> 2);
                int r0 = k0 + (lane & 3);
                bf[tn][0] = __float_as_uint(sb[r0 * BSTRIDE + n0]);
                bf[tn][1] = __float_as_uint(sb[(r0 + 4) * BSTRIDE + n0]);
            }
#pragma unroll
            for (int tm = 0; tm < 2; tm++)
#pragma unroll
                for (int tn = 0; tn < 8; tn++)
                    mma_tf32(acc[tm][tn], af[tm], bf[tn]);
        }
    }

    // -------- epilogue --------
#pragma unroll
    for (int tm = 0; tm < 2; tm++) {
        int row = bm0 + wm + tm * 16 + (lane >> 2);
#pragma unroll
        for (int tn = 0; tn < 8; tn++) {
            int col = bn0 + wn + tn * 8 + (lane & 3) * 2;
            float v0 = acc[tm][tn][0], v1 = acc[tm][tn][1];
            float v2 = acc[tm][tn][2], v3 = acc[tm][tn][3];
            if (MODE == 0 || MODE == 3) {
                float b0 = __ldg(bias + col), b1 = __ldg(bias + col + 1);
                v0 += b0; v1 += b1; v2 += b0; v3 += b1;
            }
            if (MODE == 0) {
                v0 = fmaxf(v0, 0.f); v1 = fmaxf(v1, 0.f);
                v2 = fmaxf(v2, 0.f); v3 = fmaxf(v3, 0.f);
            }
            if (row < M)     *(float2*)(C + (size_t)row * N + col)       = make_float2(v0, v1);
            if (row + 8 < M) *(float2*)(C + (size_t)(row + 8) * N + col) = make_float2(v2, v3);
        }
    }

    if (MODE == 1) {
#pragma unroll
        for (int tn = 0; tn < 8; tn++) {
            float s0 = acc[0][tn][0] + acc[0][tn][2] + acc[1][tn][0] + acc[1][tn][2];
            float s1 = acc[0][tn][1] + acc[0][tn][3] + acc[1][tn][1] + acc[1][tn][3];
            float q0 = acc[0][tn][0] * acc[0][tn][0] + acc[0][tn][2] * acc[0][tn][2]
                     + acc[1][tn][0] * acc[1][tn][0] + acc[1][tn][2] * acc[1][tn][2];
            float q1 = acc[0][tn][1] * acc[0][tn][1] + acc[0][tn][3] * acc[0][tn][3]
                     + acc[1][tn][1] * acc[1][tn][1] + acc[1][tn][3] * acc[1][tn][3];
#pragma unroll
            for (int st = 16; st >= 4; st >>= 1) {
                s0 += __shfl_down_sync(0xffffffffu, s0, st);
                s1 += __shfl_down_sync(0xffffffffu, s1, st);
                q0 += __shfl_down_sync(0xffffffffu, q0, st);
                q1 += __shfl_down_sync(0xffffffffu, q1, st);
            }
            if (lane < 4) {
                int col = bn0 + wn + tn * 8 + lane * 2;
                atomicAdd(&stats[col], s0);
                atomicAdd(&stats[col + 1], s1);
                atomicAdd(&stats[MAXC + col], q0);
                atomicAdd(&stats[MAXC + col + 1], q1);
            }
        }
    }
}

// ---------------- fp32 tiled SIMT GEMM (final MLP head — exact fp32) ----------------
#define BM 64
#define BN 64
#define BK 16
template<int RELU>
__global__ void gemm_k(const float* __restrict__ A, const float* __restrict__ B,
                       const float* __restrict__ bias, float* __restrict__ C,
                       int M, int K, int N) {
    __shared__ float As2[BK][BM];
    __shared__ float Bs2[BK][BN];
    const int tid = threadIdx.x;
    const int bcol = blockIdx.x, brow = blockIdx.y;
    const int tx = tid & 15, ty = tid >> 4;

    const int arow  = tid >> 2;
    const int acol4 = (tid & 3) * 4;
    const int brow_l = tid >> 4;
    const int bcol4  = (tid & 15) * 4;
    const int grow = brow * BM + arow;

    float acc[4][4];
#pragma unroll
    for (int i = 0; i < 4; i++)
#pragma unroll
        for (int j = 0; j < 4; j++) acc[i][j] = 0.f;

    for (int k0 = 0; k0 < K; k0 += BK) {
        float4 av = make_float4(0.f, 0.f, 0.f, 0.f);
        if (grow < M)
            av = *(const float4*)(A + (size_t)grow * K + k0 + acol4);
        As2[acol4 + 0][arow] = av.x;
        As2[acol4 + 1][arow] = av.y;
        As2[acol4 + 2][arow] = av.z;
        As2[acol4 + 3][arow] = av.w;
        float4 bv = *(const float4*)(B + (size_t)(k0 + brow_l) * N + bcol * BN + bcol4);
        *(float4*)(&Bs2[brow_l][bcol4]) = bv;
        __syncthreads();
#pragma unroll
        for (int k = 0; k < BK; k++) {
            float4 a = *(const float4*)(&As2[k][ty * 4]);
            float4 b = *(const float4*)(&Bs2[k][tx * 4]);
            float ar[4] = {a.x, a.y, a.z, a.w};
            float br[4] = {b.x, b.y, b.z, b.w};
#pragma unroll
            for (int i = 0; i < 4; i++)
#pragma unroll
                for (int j = 0; j < 4; j++)
                    acc[i][j] += ar[i] * br[j];
        }
        __syncthreads();
    }

    const int row0 = brow * BM + ty * 4;
    const int col0 = bcol * BN + tx * 4;
    float4 bb = *(const float4*)(bias + col0);
#pragma unroll
    for (int i = 0; i < 4; i++) {
        int r = row0 + i;
        if (r < M) {
            float4 v;
            v.x = acc[i][0] + bb.x; v.y = acc[i][1] + bb.y;
            v.z = acc[i][2] + bb.z; v.w = acc[i][3] + bb.w;
            if (RELU) {
                v.x = fmaxf(v.x, 0.f); v.y = fmaxf(v.y, 0.f);
                v.z = fmaxf(v.z, 0.f); v.w = fmaxf(v.w, 0.f);
            }
            *(float4*)(C + (size_t)r * N + col0) = v;
        }
    }
}

// ---------------- host-side helpers ----------------
static float* symaddrf(const void* sym) {
    void* p = nullptr;
    cudaGetSymbolAddress(&p, sym);
    return (float*)p;
}
static int* symaddri(const void* sym) {
    void* p = nullptr;
    cudaGetSymbolAddress(&p, sym);
    return (int*)p;
}

template<int MODE>
static void launch_gemm(cudaStream_t st, const float* A, const float* B, const float* bias,
                        float* stats, float* C, int M, int K, int N) {
    static int attr_done = 0;
    if (!attr_done) {
        cudaFuncSetAttribute(gemm_tf32_k<MODE>,
                             cudaFuncAttributeMaxDynamicSharedMemorySize, GEMM_SMEM);
        attr_done = 1;
    }
    dim3 grid(N / TBN, (M + TBM - 1) / TBM);
    gemm_tf32_k<MODE><<<grid, 256, GEMM_SMEM, st>>>(A, B, bias, stats, C, M, K, N);
}

extern "C" void kernel_launch(void* const* d_in, const int* in_sizes, int n_in,
                              void* d_out, int out_size) {
    const float* x     = (const float*)d_in[0];
    const int*   ei    = (const int*)d_in[1];
    const int*   batch = (const int*)d_in[2];
    const float* w0 = (const float*)d_in[3];
    const float* b0 = (const float*)d_in[4];
    const float* mw1 = (const float*)d_in[25];
    const float* mb1 = (const float*)d_in[26];
    const float* mw2 = (const float*)d_in[27];
    const float* mb2 = (const float*)d_in[28];

    const int F = 128;
    const int n = in_sizes[0] / F;          // 20000
    const int E = in_sizes[1] / 2;          // 320000
    const int* src = ei;
    const int* dst = ei + E;
    const float invn = 1.0f / (float)n;

    float* bufA = symaddrf(g_bufA);
    float* bufB = symaddrf(g_bufB);
    float* bufC = symaddrf(g_bufC);
    float* bufD = symaddrf(g_bufD);
    float* aggA = symaddrf(g_aggA);
    float* aggB = symaddrf(g_aggB);
    float* dinv = symaddrf(g_dinv);
    float* stats  = symaddrf(g_stats);
    float* stats2 = symaddrf(g_stats2);
    float* sc  = symaddrf(g_sc);
    float* sh  = symaddrf(g_sh);
    float* sc2 = symaddrf(g_sc2);
    float* sh2 = symaddrf(g_sh2);
    float* pool = symaddrf(g_pool);
    float* mlp  = symaddrf(g_mlp);
    int* cnt_i    = symaddri(g_cnt_i);
    int* rowstart = symaddri(g_rowstart);
    int* cursor   = symaddri(g_cursor);
    int* csr      = symaddri(g_csr);
    int* gstart   = symaddri(g_gstart);

    // side stream + fork/join events (created on first, uncaptured, call)
    static cudaStream_t s2 = nullptr;
    static cudaEvent_t evF[2], evJ[2], evT, evG;
    if (!s2) {
        cudaStreamCreateWithFlags(&s2, cudaStreamNonBlocking);
        for (int i = 0; i < 2; i++) {
            cudaEventCreateWithFlags(&evF[i], cudaEventDisableTiming);
            cudaEventCreateWithFlags(&evJ[i], cudaEventDisableTiming);
        }
        cudaEventCreateWithFlags(&evT, cudaEventDisableTiming);
        cudaEventCreateWithFlags(&evG, cudaEventDisableTiming);
    }

    // ---- fork s2 from capture-origin stream FIRST (capture topology rule) ----
    cudaEventRecord(evT, 0);
    cudaStreamWaitEvent(s2, evT, 0);
    gbound_k<<<2, 256, 0, s2>>>(batch, gstart, n, NGRAPH);
    cudaEventRecord(evG, s2);

    // ---- CSR build + dinv (coalesced chunked scan) ----
    cudaMemsetAsync(cnt_i, 0, n * sizeof(int), 0);
    cnt_k<<<(E + 255) / 256, 256>>>(dst, cnt_i, E);
    prefix_k<<<1, 1024>>>(cnt_i, rowstart, cursor, dinv, n);
    fill_k<<<(E + 255) / 256, 256>>>(src, dst, cursor, csr, E);

    // ---- stem: h = relu(agg(x) @ w0 + b0) ----
    launch_agg<0>(0, x, csr, rowstart, dinv, nullptr, nullptr, aggA, F, n);
    launch_gemm<0>(0, aggA, w0, b0, nullptr, bufA, n, F, 256);

    // ---- residual blocks ----
    const int Cin_arr[2]  = {256, 512};
    const int Cmid_arr[2] = {384, 768};
    const int Cout_arr[2] = {512, 1024};
    for (int blk = 0; blk < 2; blk++) {
        int base = 5 + blk * 10;
        const float* w1  = (const float*)d_in[base + 0];
        const float* g1  = (const float*)d_in[base + 2];
        const float* be1 = (const float*)d_in[base + 3];
        const float* w2  = (const float*)d_in[base + 4];
        const float* g2  = (const float*)d_in[base + 6];
        const float* be2 = (const float*)d_in[base + 7];
        const float* w3  = (const float*)d_in[base + 8];
        const float* b3  = (const float*)d_in[base + 9];
        int Cin = Cin_arr[blk], Cmid = Cmid_arr[blk], Cout = Cout_arr[blk];

        // aggA = A_hat @ h  (shared by w1 and w3)
        launch_agg<0>(0, bufA, csr, rowstart, dinv, nullptr, nullptr, aggA, Cin, n);

        // fork: w3 branch GEMM on side stream (reads aggA only)
        cudaEventRecord(evF[blk], 0);
        cudaStreamWaitEvent(s2, evF[blk], 0);
        launch_gemm<3>(s2, aggA, w3, b3, nullptr, bufD, n, Cin, Cout);
        cudaEventRecord(evJ[blk], s2);

        // main stream: w1 -> stats -> bnprep -> aggB -> w2 -> stats -> bnprep2
        cudaMemsetAsync(stats, 0, 2 * MAXC * sizeof(float), 0);
        launch_gemm<1>(0, aggA, w1, nullptr, stats, bufB, n, Cin, Cmid);
        bnprep_k<<<(Cmid + 255) / 256, 256>>>(stats, g1, be1, invn, sc, sh, Cmid);
        launch_agg<1>(0, bufB, csr, rowstart, dinv, sc, sh, aggB, Cmid, n);
        cudaMemsetAsync(stats2, 0, 2 * MAXC * sizeof(float), 0);
        launch_gemm<1>(0, aggB, w2, nullptr, stats2, bufC, n, Cmid, Cout);
        bnprep_k<<<(Cout + 255) / 256, 256>>>(stats2, g2, be2, invn, sc2, sh2, Cout);

        // join
        cudaStreamWaitEvent(0, evJ[blk], 0);
        if (blk == 0) {
            int total4 = n * (Cout / 4);
            join_k<<<(total4 + 255) / 256, 256>>>(bufD, bufC, sc2, sh2, bufA, total4, Cout / 4);
        } else {
            cudaStreamWaitEvent(0, evG, 0);
            dim3 pg(4, NGRAPH);
            pool_fused_k<<<pg, 256>>>(bufD, bufC, sc2, sh2, gstart, pool);
        }
    }

    // ---- MLP head in exact fp32 (tf32 here pushed rel_err past the 1e-3 gate) ----
    {
        dim3 gmm1(1024 / BN, (NGRAPH + BM - 1) / BM);
        gemm_k<1><<<gmm1, 256>>>(pool, mw1, mb1, mlp, NGRAPH, 1024, 1024);
        dim3 gmm2(768 / BN, (NGRAPH + BM - 1) / BM);
        gemm_k<0><<<gmm2, 256>>>(mlp, mw2, mb2, (float*)d_out, NGRAPH, 1024, 768);
    }
}

// round 17
// speedup vs baseline: 1.0658x; 1.0367x over previous
#include <cuda_runtime.h>
#include <cstdint>

// ---------------- problem constants ----------------
#define MAXN 20000
#define MAXE 512000
#define MAXC 1024
#define NGRAPH 256
#define EPS 1e-5f

// ---------------- scratch (static device memory; no allocs) ----------------
__device__ float g_bufA[(size_t)MAXN * MAXC];   // h
__device__ float g_bufB[(size_t)MAXN * MAXC];   // t raw (pre-BN)
__device__ float g_bufC[(size_t)MAXN * MAXC];   // u raw (pre-BN)
__device__ float g_bufD[(size_t)MAXN * MAXC];   // w3 branch raw (+bias)
__device__ float g_aggA[(size_t)MAXN * 512];
__device__ float g_aggB[(size_t)MAXN * 768];
__device__ float g_dinv[MAXN];
__device__ float g_statsA[4 * 2 * MAXC];        // 4 slices of [sum | sumsq], pre-zeroed
__device__ float g_sc [MAXC];
__device__ float g_sh [MAXC];
__device__ float g_sc2[MAXC];
__device__ float g_sh2[MAXC];
__device__ float g_pool[NGRAPH * MAXC];
__device__ float g_mlp [NGRAPH * MAXC];
__device__ int   g_cnt_i[MAXN];
__device__ int   g_rowstart[MAXN + 1];
__device__ int   g_cursor[MAXN];
__device__ int   g_csr[MAXE];
__device__ int   g_gstart[NGRAPH + 1];

// ---------------- graph preprocessing ----------------
__global__ void cnt_k(const int* __restrict__ dst, int* __restrict__ cnt, int E) {
    int i = blockIdx.x * blockDim.x + threadIdx.x;
    if (i < E) atomicAdd(&cnt[dst[i]], 1);
}
// chunked coalesced block scan: 1024 threads, chunks of 1024 elements, running carry
__global__ void prefix_k(const int* __restrict__ cnt, int* __restrict__ rowstart,
                         int* __restrict__ cursor, float* __restrict__ dinv, int n) {
    __shared__ int warpsums[32];
    __shared__ int s_carry;
    const int t = threadIdx.x;
    const int lane = t & 31, wid = t >> 5;
    if (t == 0) s_carry = 0;
    __syncthreads();
    for (int base = 0; base < n; base += 1024) {
        int idx = base + t;
        int v = (idx < n) ? cnt[idx] : 0;
        int x = v;
#pragma unroll
        for (int off = 1; off < 32; off <<= 1) {
            int y = __shfl_up_sync(0xffffffffu, x, off);
            if (lane >= off) x += y;
        }
        if (lane == 31) warpsums[wid] = x;
        __syncthreads();
        if (wid == 0) {
            int w = warpsums[lane];
#pragma unroll
            for (int off = 1; off < 32; off <<= 1) {
                int y = __shfl_up_sync(0xffffffffu, w, off);
                if (lane >= off) w += y;
            }
            warpsums[lane] = w;
        }
        __syncthreads();
        int excl = s_carry + (wid > 0 ? warpsums[wid - 1] : 0) + x - v;
        if (idx < n) {
            rowstart[idx] = excl;
            cursor[idx] = excl;
            dinv[idx] = rsqrtf(1.0f + (float)v);
        }
        __syncthreads();
        if (t == 1023) s_carry += warpsums[31];
        __syncthreads();
    }
    if (t == 0) rowstart[n] = s_carry;
}
__global__ void fill_k(const int* __restrict__ src, const int* __restrict__ dst,
                       int* __restrict__ cursor, int* __restrict__ csr, int E) {
    int e = blockIdx.x * blockDim.x + threadIdx.x;
    if (e < E) {
        int pos = atomicAdd(&cursor[dst[e]], 1);
        csr[pos] = src[e];
    }
}
__global__ void gbound_k(const int* __restrict__ batch, int* __restrict__ gstart, int n, int G) {
    int g = blockIdx.x * blockDim.x + threadIdx.x;
    if (g > G) return;
    int lo = 0, hi = n;
    while (lo < hi) {
        int mid = (lo + hi) >> 1;
        if (batch[mid] < g) lo = mid + 1; else hi = mid;
    }
    gstart[g] = lo;
}
__global__ void bnprep_k(const float* __restrict__ stats, const float* __restrict__ gam,
                         const float* __restrict__ bet, float invn,
                         float* __restrict__ sc, float* __restrict__ sh, int C) {
    int c = blockIdx.x * blockDim.x + threadIdx.x;
    if (c >= C) return;
    float m = stats[c] * invn;
    float s = gam[c] * rsqrtf(stats[MAXC + c] * invn - m * m + EPS);
    sc[c] = s;
    sh[c] = bet[c] - m * s;
}

// ---------------- pre-GEMM aggregation (multi-row blocks) ----------------
// MODE 0: plain; MODE 1: gathered elements pass relu(v*sc+sh) first (fused BN apply)
template<int MODE>
__global__ void aggregate_k(const float* __restrict__ h, const int* __restrict__ csr,
                            const int* __restrict__ rowstart, const float* __restrict__ dinv,
                            const float* __restrict__ sc, const float* __restrict__ sh,
                            float* __restrict__ out, int C4, int n) {
    const int rpb = blockDim.x / C4;
    const int rloc = threadIdx.x / C4;
    const int t = threadIdx.x - rloc * C4;
    const int r = blockIdx.x * rpb + rloc;
    if (r >= n) return;
    const float4* base = (const float4*)h;

    float4 sc4, sh4;
    if (MODE == 1) {
        sc4 = *(const float4*)(sc + t * 4);
        sh4 = *(const float4*)(sh + t * 4);
    }

    const float dr = __ldg(&dinv[r]);
    float4 v = base[(size_t)r * C4 + t];
    if (MODE == 1) {
        v.x = fmaxf(v.x * sc4.x + sh4.x, 0.f);
        v.y = fmaxf(v.y * sc4.y + sh4.y, 0.f);
        v.z = fmaxf(v.z * sc4.z + sh4.z, 0.f);
        v.w = fmaxf(v.w * sc4.w + sh4.w, 0.f);
    }
    float4 acc = make_float4(v.x * dr, v.y * dr, v.z * dr, v.w * dr);

    int j   = __ldg(&rowstart[r]);
    int end = __ldg(&rowstart[r + 1]);
    for (; j < end; j++) {
        int s0 = __ldg(&csr[j]);
        float d0 = __ldg(&dinv[s0]);
        float4 v0 = base[(size_t)s0 * C4 + t];
        if (MODE == 1) {
            v0.x = fmaxf(v0.x * sc4.x + sh4.x, 0.f);
            v0.y = fmaxf(v0.y * sc4.y + sh4.y, 0.f);
            v0.z = fmaxf(v0.z * sc4.z + sh4.z, 0.f);
            v0.w = fmaxf(v0.w * sc4.w + sh4.w, 0.f);
        }
        acc.x += v0.x * d0; acc.y += v0.y * d0;
        acc.z += v0.z * d0; acc.w += v0.w * d0;
    }
    float4 o = make_float4(acc.x * dr, acc.y * dr, acc.z * dr, acc.w * dr);
    ((float4*)out)[(size_t)r * C4 + t] = o;
}

template<int MODE>
static void launch_agg(cudaStream_t st, const float* h, const int* csr, const int* rowstart,
                       const float* dinv, const float* sc, const float* sh,
                       float* out, int C, int n) {
    int C4 = C / 4;
    int R = 256 / C4; if (R < 1) R = 1;
    int block = C4 * R;
    int grid = (n + R - 1) / R;
    aggregate_k<MODE><<<grid, block, 0, st>>>(h, csr, rowstart, dinv, sc, sh, out, C4, n);
}

// ---------------- residual join (blk0): out = d + relu(c*sc + sh) ----------------
__global__ void join_k(const float* __restrict__ d, const float* __restrict__ c,
                       const float* __restrict__ sc, const float* __restrict__ sh,
                       float* __restrict__ out, int total4, int C4) {
    int idx = blockIdx.x * blockDim.x + threadIdx.x;
    if (idx >= total4) return;
    int t = idx % C4;
    float4 dv = ((const float4*)d)[idx];
    float4 cv = ((const float4*)c)[idx];
    float4 s4 = *(const float4*)(sc + t * 4);
    float4 h4 = *(const float4*)(sh + t * 4);
    float4 o;
    o.x = dv.x + fmaxf(cv.x * s4.x + h4.x, 0.f);
    o.y = dv.y + fmaxf(cv.y * s4.y + h4.y, 0.f);
    o.z = dv.z + fmaxf(cv.z * s4.z + h4.z, 0.f);
    o.w = dv.w + fmaxf(cv.w * s4.w + h4.w, 0.f);
    ((float4*)out)[idx] = o;
}

// ---------------- fused join + segmented mean pool (blk1, C=1024) ----------------
// grid (4, NGRAPH): each CTA covers 64 float4 columns of one graph;
// 256 threads = 4 row-groups x 64 col-threads, smem reduction across row-groups.
__global__ void pool_fused_k(const float* __restrict__ d, const float* __restrict__ c,
                             const float* __restrict__ sc, const float* __restrict__ sh,
                             const int* __restrict__ gstart, float* __restrict__ pooled) {
    __shared__ float4 red[256];
    const int g  = blockIdx.y;
    const int cb = blockIdx.x * 64;
    const int rg = threadIdx.x >> 6;
    const int cl = threadIdx.x & 63;
    const int t  = cb + cl;
    const float4 s4 = *(const float4*)(sc + t * 4);
    const float4 h4 = *(const float4*)(sh + t * 4);
    int rs = __ldg(&gstart[g]), re = __ldg(&gstart[g + 1]);
    float4 acc = make_float4(0.f, 0.f, 0.f, 0.f);
    for (int r = rs + rg; r < re; r += 4) {
        float4 dv = ((const float4*)d)[(size_t)r * 256 + t];
        float4 cv = ((const float4*)c)[(size_t)r * 256 + t];
        acc.x += dv.x + fmaxf(cv.x * s4.x + h4.x, 0.f);
        acc.y += dv.y + fmaxf(cv.y * s4.y + h4.y, 0.f);
        acc.z += dv.z + fmaxf(cv.z * s4.z + h4.z, 0.f);
        acc.w += dv.w + fmaxf(cv.w * s4.w + h4.w, 0.f);
    }
    red[threadIdx.x] = acc;
    __syncthreads();
    if (rg == 0) {
#pragma unroll
        for (int q = 1; q < 4; q++) {
            float4 v = red[q * 64 + cl];
            acc.x += v.x; acc.y += v.y; acc.z += v.z; acc.w += v.w;
        }
        float inv = (re > rs) ? 1.0f / (float)(re - rs) : 0.f;
        float4 o = make_float4(acc.x * inv, acc.y * inv, acc.z * inv, acc.w * inv);
        ((float4*)pooled)[g * 256 + t] = o;
    }
}

// =================== TF32 tensor-core GEMM (256 thr, 4 stages) =====
// MODE 0: C = A@B + bias, relu
// MODE 1: C = A@B raw; atomic col sums into stats [sum | sumsq]
// MODE 3: C = A@B + bias
#define TBM 128
#define TBN 128
#define TBK 16
#define STAGES 4
#define ASTRIDE 20
#define BSTRIDE 136
#define A_TILE (TBM * ASTRIDE)
#define B_TILE (TBK * BSTRIDE)
#define STAGE_FLOATS (A_TILE + B_TILE)
#define GEMM_SMEM (STAGES * STAGE_FLOATS * 4)

__device__ __forceinline__ void cp_async16(uint32_t saddr, const void* gaddr, int srcsize) {
    asm volatile("cp.async.cg.shared.global [%0], [%1], 16, %2;"
                 :: "r"(saddr), "l"(gaddr), "r"(srcsize));
}
__device__ __forceinline__ void mma_tf32(float* c, const uint32_t* a, const uint32_t* b) {
    asm volatile(
        "mma.sync.aligned.m16n8k8.row.col.f32.tf32.tf32.f32 "
        "{%0,%1,%2,%3}, {%4,%5,%6,%7}, {%8,%9}, {%0,%1,%2,%3};\n"
        : "+f"(c[0]), "+f"(c[1]), "+f"(c[2]), "+f"(c[3])
        : "r"(a[0]), "r"(a[1]), "r"(a[2]), "r"(a[3]), "r"(b[0]), "r"(b[1]));
}

__device__ __forceinline__ void load_tile(float* stage, const float* A, const float* B,
                                          int M, int K, int N, int bm0, int bn0, int k0,
                                          int tid) {
    float* sa = stage;
    float* sb = stage + A_TILE;
#pragma unroll
    for (int l = 0; l < 2; l++) {
        int idx = tid + l * 256;
        int arow = idx >> 2, ac4 = (idx & 3) * 4;
        const float* ga = A + (size_t)(bm0 + arow) * K + k0 + ac4;
        uint32_t da = (uint32_t)__cvta_generic_to_shared(sa + arow * ASTRIDE + ac4);
        cp_async16(da, ga, (bm0 + arow) < M ? 16 : 0);
        int bk = idx >> 5, bn4 = (idx & 31) * 4;
        const float* gb = B + (size_t)(k0 + bk) * N + bn0 + bn4;
        uint32_t db = (uint32_t)__cvta_generic_to_shared(sb + bk * BSTRIDE + bn4);
        cp_async16(db, gb, 16);
    }
}

template<int MODE>
__global__ __launch_bounds__(256, 2)
void gemm_tf32_k(const float* __restrict__ A, const float* __restrict__ B,
                 const float* __restrict__ bias,
                 float* __restrict__ stats,
                 float* __restrict__ C, int M, int K, int N) {
    extern __shared__ float sm[];
    const int tid  = threadIdx.x;
    const int lane = tid & 31;
    const int wid  = tid >> 5;
    const int wm   = (wid & 3) * 32;
    const int wn   = (wid >> 2) * 64;
    const int bm0  = blockIdx.y * TBM;
    const int bn0  = blockIdx.x * TBN;

    float acc[2][8][4];
#pragma unroll
    for (int i = 0; i < 2; i++)
#pragma unroll
        for (int j = 0; j < 8; j++)
#pragma unroll
            for (int l = 0; l < 4; l++) acc[i][j][l] = 0.f;

    const int ktiles = K / TBK;

#pragma unroll
    for (int s = 0; s < STAGES - 1; s++) {
        load_tile(sm + s * STAGE_FLOATS, A, B, M, K, N, bm0, bn0, s * TBK, tid);
        asm volatile("cp.async.commit_group;");
    }

    for (int kt = 0; kt < ktiles; kt++) {
        asm volatile("cp.async.wait_group %0;" :: "n"(STAGES - 2));
        __syncthreads();

        int nk = kt + STAGES - 1;
        if (nk < ktiles)
            load_tile(sm + (nk % STAGES) * STAGE_FLOATS, A, B, M, K, N, bm0, bn0, nk * TBK, tid);
        asm volatile("cp.async.commit_group;");

        const float* sa = sm + (kt % STAGES) * STAGE_FLOATS;
        const float* sb = sa + A_TILE;
#pragma unroll
        for (int ks = 0; ks < 2; ks++) {
            const int k0 = ks * 8;
            uint32_t af[2][4], bf[8][2];
#pragma unroll
            for (int tm = 0; tm < 2; tm++) {
                int r0 = wm + tm * 16 + (lane >> 2);
                int c0 = k0 + (lane & 3);
                af[tm][0] = __float_as_uint(sa[r0 * ASTRIDE + c0]);
                af[tm][1] = __float_as_uint(sa[(r0 + 8) * ASTRIDE + c0]);
                af[tm][2] = __float_as_uint(sa[r0 * ASTRIDE + c0 + 4]);
                af[tm][3] = __float_as_uint(sa[(r0 + 8) * ASTRIDE + c0 + 4]);
            }
#pragma unroll
            for (int tn = 0; tn < 8; tn++) {
                int n0 = wn + tn * 8 + (lane >> 2);
                int r0 = k0 + (lane & 3);
                bf[tn][0] = __float_as_uint(sb[r0 * BSTRIDE + n0]);
                bf[tn][1] = __float_as_uint(sb[(r0 + 4) * BSTRIDE + n0]);
            }
#pragma unroll
            for (int tm = 0; tm < 2; tm++)
#pragma unroll
                for (int tn = 0; tn < 8; tn++)
                    mma_tf32(acc[tm][tn], af[tm], bf[tn]);
        }
    }

    // -------- epilogue --------
#pragma unroll
    for (int tm = 0; tm < 2; tm++) {
        int row = bm0 + wm + tm * 16 + (lane >> 2);
#pragma unroll
        for (int tn = 0; tn < 8; tn++) {
            int col = bn0 + wn + tn * 8 + (lane & 3) * 2;
            float v0 = acc[tm][tn][0], v1 = acc[tm][tn][1];
            float v2 = acc[tm][tn][2], v3 = acc[tm][tn][3];
            if (MODE == 0 || MODE == 3) {
                float b0 = __ldg(bias + col), b1 = __ldg(bias + col + 1);
                v0 += b0; v1 += b1; v2 += b0; v3 += b1;
            }
            if (MODE == 0) {
                v0 = fmaxf(v0, 0.f); v1 = fmaxf(v1, 0.f);
                v2 = fmaxf(v2, 0.f); v3 = fmaxf(v3, 0.f);
            }
            if (row < M)     *(float2*)(C + (size_t)row * N + col)       = make_float2(v0, v1);
            if (row + 8 < M) *(float2*)(C + (size_t)(row + 8) * N + col) = make_float2(v2, v3);
        }
    }

    if (MODE == 1) {
#pragma unroll
        for (int tn = 0; tn < 8; tn++) {
            float s0 = acc[0][tn][0] + acc[0][tn][2] + acc[1][tn][0] + acc[1][tn][2];
            float s1 = acc[0][tn][1] + acc[0][tn][3] + acc[1][tn][1] + acc[1][tn][3];
            float q0 = acc[0][tn][0] * acc[0][tn][0] + acc[0][tn][2] * acc[0][tn][2]
                     + acc[1][tn][0] * acc[1][tn][0] + acc[1][tn][2] * acc[1][tn][2];
            float q1 = acc[0][tn][1] * acc[0][tn][1] + acc[0][tn][3] * acc[0][tn][3]
                     + acc[1][tn][1] * acc[1][tn][1] + acc[1][tn][3] * acc[1][tn][3];
#pragma unroll
            for (int st = 16; st >= 4; st >>= 1) {
                s0 += __shfl_down_sync(0xffffffffu, s0, st);
                s1 += __shfl_down_sync(0xffffffffu, s1, st);
                q0 += __shfl_down_sync(0xffffffffu, q0, st);
                q1 += __shfl_down_sync(0xffffffffu, q1, st);
            }
            if (lane < 4) {
                int col = bn0 + wn + tn * 8 + lane * 2;
                atomicAdd(&stats[col], s0);
                atomicAdd(&stats[col + 1], s1);
                atomicAdd(&stats[MAXC + col], q0);
                atomicAdd(&stats[MAXC + col + 1], q1);
            }
        }
    }
}

// ---------------- fp32 SIMT GEMM, BM=32 (MLP head — exact fp32, more CTAs) ----------
#define HBM2 32
#define HBN2 64
#define HBK2 16
template<int RELU>
__global__ void gemm_head_k(const float* __restrict__ A, const float* __restrict__ B,
                            const float* __restrict__ bias, float* __restrict__ C,
                            int M, int K, int N) {
    __shared__ float As2[HBK2][HBM2];
    __shared__ float Bs2[HBK2][HBN2];
    const int tid = threadIdx.x;              // 128 threads
    const int bcol = blockIdx.x, brow = blockIdx.y;
    const int tx = tid & 15, ty = tid >> 4;   // tx 0..15 (cols of 4), ty 0..7 (rows of 4)

    const int arow  = tid >> 2;               // 0..31
    const int acol4 = (tid & 3) * 4;
    const int grow = brow * HBM2 + arow;

    float acc[4][4];
#pragma unroll
    for (int i = 0; i < 4; i++)
#pragma unroll
        for (int j = 0; j < 4; j++) acc[i][j] = 0.f;

    for (int k0 = 0; k0 < K; k0 += HBK2) {
        float4 av = make_float4(0.f, 0.f, 0.f, 0.f);
        if (grow < M)
            av = *(const float4*)(A + (size_t)grow * K + k0 + acol4);
        As2[acol4 + 0][arow] = av.x;
        As2[acol4 + 1][arow] = av.y;
        As2[acol4 + 2][arow] = av.z;
        As2[acol4 + 3][arow] = av.w;
#pragma unroll
        for (int l = 0; l < 2; l++) {
            int idx = tid + l * 128;
            int brow_l = idx >> 4, bcol4 = (idx & 15) * 4;
            float4 bv = *(const float4*)(B + (size_t)(k0 + brow_l) * N + bcol * HBN2 + bcol4);
            *(float4*)(&Bs2[brow_l][bcol4]) = bv;
        }
        __syncthreads();
#pragma unroll
        for (int k = 0; k < HBK2; k++) {
            float4 a = *(const float4*)(&As2[k][ty * 4]);
            float4 b = *(const float4*)(&Bs2[k][tx * 4]);
            float ar[4] = {a.x, a.y, a.z, a.w};
            float br[4] = {b.x, b.y, b.z, b.w};
#pragma unroll
            for (int i = 0; i < 4; i++)
#pragma unroll
                for (int j = 0; j < 4; j++)
                    acc[i][j] += ar[i] * br[j];
        }
        __syncthreads();
    }

    const int row0 = brow * HBM2 + ty * 4;
    const int col0 = bcol * HBN2 + tx * 4;
    float4 bb = *(const float4*)(bias + col0);
#pragma unroll
    for (int i = 0; i < 4; i++) {
        int r = row0 + i;
        if (r < M) {
            float4 v;
            v.x = acc[i][0] + bb.x; v.y = acc[i][1] + bb.y;
            v.z = acc[i][2] + bb.z; v.w = acc[i][3] + bb.w;
            if (RELU) {
                v.x = fmaxf(v.x, 0.f); v.y = fmaxf(v.y, 0.f);
                v.z = fmaxf(v.z, 0.f); v.w = fmaxf(v.w, 0.f);
            }
            *(float4*)(C + (size_t)r * N + col0) = v;
        }
    }
}

// ---------------- host-side helpers ----------------
static float* symaddrf(const void* sym) {
    void* p = nullptr;
    cudaGetSymbolAddress(&p, sym);
    return (float*)p;
}
static int* symaddri(const void* sym) {
    void* p = nullptr;
    cudaGetSymbolAddress(&p, sym);
    return (int*)p;
}

template<int MODE>
static void launch_gemm(cudaStream_t st, const float* A, const float* B, const float* bias,
                        float* stats, float* C, int M, int K, int N) {
    static int attr_done = 0;
    if (!attr_done) {
        cudaFuncSetAttribute(gemm_tf32_k<MODE>,
                             cudaFuncAttributeMaxDynamicSharedMemorySize, GEMM_SMEM);
        attr_done = 1;
    }
    dim3 grid(N / TBN, (M + TBM - 1) / TBM);
    gemm_tf32_k<MODE><<<grid, 256, GEMM_SMEM, st>>>(A, B, bias, stats, C, M, K, N);
}

extern "C" void kernel_launch(void* const* d_in, const int* in_sizes, int n_in,
                              void* d_out, int out_size) {
    const float* x     = (const float*)d_in[0];
    const int*   ei    = (const int*)d_in[1];
    const int*   batch = (const int*)d_in[2];
    const float* w0 = (const float*)d_in[3];
    const float* b0 = (const float*)d_in[4];
    const float* mw1 = (const float*)d_in[25];
    const float* mb1 = (const float*)d_in[26];
    const float* mw2 = (const float*)d_in[27];
    const float* mb2 = (const float*)d_in[28];

    const int F = 128;
    const int n = in_sizes[0] / F;          // 20000
    const int E = in_sizes[1] / 2;          // 320000
    const int* src = ei;
    const int* dst = ei + E;
    const float invn = 1.0f / (float)n;

    float* bufA = symaddrf(g_bufA);
    float* bufB = symaddrf(g_bufB);
    float* bufC = symaddrf(g_bufC);
    float* bufD = symaddrf(g_bufD);
    float* aggA = symaddrf(g_aggA);
    float* aggB = symaddrf(g_aggB);
    float* dinv = symaddrf(g_dinv);
    float* statsA = symaddrf(g_statsA);
    float* sc  = symaddrf(g_sc);
    float* sh  = symaddrf(g_sh);
    float* sc2 = symaddrf(g_sc2);
    float* sh2 = symaddrf(g_sh2);
    float* pool = symaddrf(g_pool);
    float* mlp  = symaddrf(g_mlp);
    int* cnt_i    = symaddri(g_cnt_i);
    int* rowstart = symaddri(g_rowstart);
    int* cursor   = symaddri(g_cursor);
    int* csr      = symaddri(g_csr);
    int* gstart   = symaddri(g_gstart);

    // side stream + fork/join events (created on first, uncaptured, call)
    static cudaStream_t s2 = nullptr;
    static cudaEvent_t evF[2], evJ[2], evT, evG;
    if (!s2) {
        cudaStreamCreateWithFlags(&s2, cudaStreamNonBlocking);
        for (int i = 0; i < 2; i++) {
            cudaEventCreateWithFlags(&evF[i], cudaEventDisableTiming);
            cudaEventCreateWithFlags(&evJ[i], cudaEventDisableTiming);
        }
        cudaEventCreateWithFlags(&evT, cudaEventDisableTiming);
        cudaEventCreateWithFlags(&evG, cudaEventDisableTiming);
    }

    // ---- fork s2 from capture-origin stream FIRST (capture topology rule) ----
    cudaEventRecord(evT, 0);
    cudaStreamWaitEvent(s2, evT, 0);
    gbound_k<<<2, 256, 0, s2>>>(batch, gstart, n, NGRAPH);
    cudaEventRecord(evG, s2);

    // ---- zero all 4 stat slices once, off the per-block critical path ----
    cudaMemsetAsync(statsA, 0, 4 * 2 * MAXC * sizeof(float), 0);

    // ---- CSR build + dinv (coalesced chunked scan) ----
    cudaMemsetAsync(cnt_i, 0, n * sizeof(int), 0);
    cnt_k<<<(E + 255) / 256, 256>>>(dst, cnt_i, E);
    prefix_k<<<1, 1024>>>(cnt_i, rowstart, cursor, dinv, n);
    fill_k<<<(E + 255) / 256, 256>>>(src, dst, cursor, csr, E);

    // ---- stem: h = relu(agg(x) @ w0 + b0) ----
    launch_agg<0>(0, x, csr, rowstart, dinv, nullptr, nullptr, aggA, F, n);
    launch_gemm<0>(0, aggA, w0, b0, nullptr, bufA, n, F, 256);

    // ---- residual blocks ----
    const int Cin_arr[2]  = {256, 512};
    const int Cmid_arr[2] = {384, 768};
    const int Cout_arr[2] = {512, 1024};
    for (int blk = 0; blk < 2; blk++) {
        int base = 5 + blk * 10;
        const float* w1  = (const float*)d_in[base + 0];
        const float* g1  = (const float*)d_in[base + 2];
        const float* be1 = (const float*)d_in[base + 3];
        const float* w2  = (const float*)d_in[base + 4];
        const float* g2  = (const float*)d_in[base + 6];
        const float* be2 = (const float*)d_in[base + 7];
        const float* w3  = (const float*)d_in[base + 8];
        const float* b3  = (const float*)d_in[base + 9];
        int Cin = Cin_arr[blk], Cmid = Cmid_arr[blk], Cout = Cout_arr[blk];
        float* st1 = statsA + (blk * 2 + 0) * 2 * MAXC;
        float* st2 = statsA + (blk * 2 + 1) * 2 * MAXC;

        // aggA = A_hat @ h  (shared by w1 and w3)
        launch_agg<0>(0, bufA, csr, rowstart, dinv, nullptr, nullptr, aggA, Cin, n);

        // fork: w3 branch GEMM on side stream (reads aggA only)
        cudaEventRecord(evF[blk], 0);
        cudaStreamWaitEvent(s2, evF[blk], 0);
        launch_gemm<3>(s2, aggA, w3, b3, nullptr, bufD, n, Cin, Cout);
        cudaEventRecord(evJ[blk], s2);

        // main stream: w1 -> bnprep -> aggB -> w2 -> bnprep2  (stats pre-zeroed)
        launch_gemm<1>(0, aggA, w1, nullptr, st1, bufB, n, Cin, Cmid);
        bnprep_k<<<(Cmid + 255) / 256, 256>>>(st1, g1, be1, invn, sc, sh, Cmid);
        launch_agg<1>(0, bufB, csr, rowstart, dinv, sc, sh, aggB, Cmid, n);
        launch_gemm<1>(0, aggB, w2, nullptr, st2, bufC, n, Cmid, Cout);
        bnprep_k<<<(Cout + 255) / 256, 256>>>(st2, g2, be2, invn, sc2, sh2, Cout);

        // join
        cudaStreamWaitEvent(0, evJ[blk], 0);
        if (blk == 0) {
            int total4 = n * (Cout / 4);
            join_k<<<(total4 + 255) / 256, 256>>>(bufD, bufC, sc2, sh2, bufA, total4, Cout / 4);
        } else {
            cudaStreamWaitEvent(0, evG, 0);
            dim3 pg(4, NGRAPH);
            pool_fused_k<<<pg, 256>>>(bufD, bufC, sc2, sh2, gstart, pool);
        }
    }

    // ---- MLP head in exact fp32 (tf32 here pushed rel_err past the 1e-3 gate);
    //      BM=32 tiles for 2x CTA parallelism on the small-M head ----
    {
        dim3 gmm1(1024 / HBN2, (NGRAPH + HBM2 - 1) / HBM2);   // (16, 8)
        gemm_head_k<1><<<gmm1, 128>>>(pool, mw1, mb1, mlp, NGRAPH, 1024, 1024);
        dim3 gmm2(768 / HBN2, (NGRAPH + HBM2 - 1) / HBM2);    // (12, 8)
        gemm_head_k<0><<<gmm2, 128>>>(mlp, mw2, mb2, (float*)d_out, NGRAPH, 1024, 768);
    }
}